// round 11
// baseline (speedup 1.0000x reference)
#include <cuda_runtime.h>
#include <cuda_fp16.h>
#include <math.h>
#include <stdint.h>

#define BB 32
#define LL 256
#define DD 128
#define GG 512

__device__ float g_xw  [BB*LL*GG];
__device__ float g_pre [BB*LL*GG];
__device__ float g_oseq[BB*LL*DD];
__device__ float g_E   [DD*GG];
// fp16, transposed, rank-sliced, gate-permuted recurrent weights:
// g_W2Th[r][c][k], c = g*32 + jj (global col = g*128 + r*32 + jj), k: 0..127 Uw, 128..255 F
__device__ __align__(16) __half g_W2Th[4*128*256];
__device__ __align__(16) __half g_URh [4*128*128];
__device__ float g_cvec[GG];

__device__ __forceinline__ float hsig(float x) {
    return fminf(fmaxf(0.2f*x + 0.5f, 0.0f), 1.0f);
}
// fast tanh via MUFU exp: max err ~1e-6, saturates correctly at both ends
__device__ __forceinline__ float tanh_fast(float x) {
    float e = __expf(fminf(2.0f*x, 80.0f));
    return 1.0f - __fdividef(2.0f, e + 1.0f);
}
__device__ __forceinline__ uint32_t smem_u32(const void* p) {
    uint32_t a;
    asm("{ .reg .u64 t; cvta.to.shared.u64 t, %1; cvt.u32.u64 %0, t; }" : "=r"(a) : "l"(p));
    return a;
}
__device__ __forceinline__ uint32_t ctarank() {
    uint32_t r; asm("mov.u32 %0, %%cluster_ctarank;" : "=r"(r)); return r;
}
__device__ __forceinline__ uint32_t mapa_u32(uint32_t a, uint32_t rk) {
    uint32_t o; asm("mapa.shared::cluster.u32 %0, %1, %2;" : "=r"(o) : "r"(a), "r"(rk)); return o;
}
__device__ __forceinline__ void mbar_init(uint32_t a, uint32_t cnt) {
    asm volatile("mbarrier.init.shared.b64 [%0], %1;" :: "r"(a), "r"(cnt) : "memory");
}
__device__ __forceinline__ void mbar_arrive_expect(uint32_t a, uint32_t tx) {
    asm volatile("mbarrier.arrive.expect_tx.shared.b64 _, [%0], %1;" :: "r"(a), "r"(tx) : "memory");
}
__device__ __forceinline__ void mbar_wait(uint32_t a, uint32_t parity) {
    uint32_t done;
    asm volatile("{\n\t.reg .pred p;\n\t"
        "mbarrier.try_wait.parity.acquire.cta.shared::cta.b64 p, [%1], %2;\n\t"
        "selp.b32 %0, 1, 0, p;\n\t}" : "=r"(done) : "r"(a), "r"(parity) : "memory");
    if (!done) {
        asm volatile("{\n\t.reg .pred P1;\n\tWL_%=:\n\t"
            "mbarrier.try_wait.parity.acquire.cta.shared::cta.b64 P1, [%0], %1, 0x989680;\n\t"
            "@P1 bra.uni WD_%=;\n\tbra.uni WL_%=;\n\tWD_%=:\n\t}"
            :: "r"(a), "r"(parity) : "memory");
    }
}
__device__ __forceinline__ void st_async_f32(uint32_t ra, float v, uint32_t rmb) {
    asm volatile("st.async.shared::cluster.mbarrier::complete_tx::bytes.b32 [%0], %1, [%2];"
                 :: "r"(ra), "r"(__float_as_uint(v)), "r"(rmb) : "memory");
}
__device__ __forceinline__ void st_async_f64(uint32_t ra, float a, float b, uint32_t rmb) {
    unsigned long long v = ((unsigned long long)__float_as_uint(b) << 32) | __float_as_uint(a);
    asm volatile("st.async.shared::cluster.mbarrier::complete_tx::bytes.b64 [%0], %1, [%2];"
                 :: "r"(ra), "l"(v), "r"(rmb) : "memory");
}
#define CLUSTER_SYNC_() do { \
    asm volatile("barrier.cluster.arrive.aligned;" ::: "memory"); \
    asm volatile("barrier.cluster.wait.aligned;" ::: "memory"); } while (0)

// batched reduce of 8 per-lane col-partials -> dst[0..7] full sums
__device__ __forceinline__ void red8_store(float* p, int lane, float* dst) {
    #pragma unroll
    for (int ofs = 16, n = 8; ofs >= 4; ofs >>= 1, n >>= 1) {
        int half = n >> 1;
        bool side = (lane & ofs) != 0;
        #pragma unroll
        for (int i = 0; i < 4; i++) {
            if (i < half) {
                float send = side ? p[i] : p[i + half];
                float recv = __shfl_xor_sync(0xffffffffu, send, ofs);
                p[i] = (side ? p[i + half] : p[i]) + recv;
            }
        }
    }
    p[0] += __shfl_xor_sync(0xffffffffu, p[0], 2);
    p[0] += __shfl_xor_sync(0xffffffffu, p[0], 1);
    if ((lane & 3) == 0) dst[(lane >> 2) & 7] = p[0];
}

// fp16 GEMV inner
__device__ __forceinline__ float dot4_h(uint2 w, float4 hv) {
    float2 a = __half22float2(*reinterpret_cast<__half2*>(&w.x));
    float2 b = __half22float2(*reinterpret_cast<__half2*>(&w.y));
    return hv.x*a.x + hv.y*a.y + hv.z*b.x + hv.w*b.y;
}

// ---------------- GEMM: C[M,512] = A[M,128] @ W[128,512] + bias ------------
__global__ void __launch_bounds__(256) gemm_k128_n512(
        const float* __restrict__ A, const float* __restrict__ W,
        const float* __restrict__ bias, float* __restrict__ C)
{
    __shared__ __align__(16) float As[64][68];
    __shared__ __align__(16) float Ws[64][64];
    int tid = threadIdx.x, tx = tid & 15, ty = tid >> 4;
    int n0 = blockIdx.x * 64;
    long r0 = (long)blockIdx.y * 64;
    float acc[4][4] = {};
    for (int kc = 0; kc < 128; kc += 64) {
        #pragma unroll
        for (int i = 0; i < 4; i++) {
            int f = tid + i*256, row = f >> 4, c4 = (f & 15) * 4;
            *reinterpret_cast<float4*>(&As[row][c4]) =
                *reinterpret_cast<const float4*>(A + (r0 + row)*128 + kc + c4);
            *reinterpret_cast<float4*>(&Ws[row][c4]) =
                *reinterpret_cast<const float4*>(W + (long)(kc + row)*GG + n0 + c4);
        }
        __syncthreads();
        #pragma unroll
        for (int k = 0; k < 64; k++) {
            float4 wv = *reinterpret_cast<const float4*>(&Ws[k][tx*4]);
            #pragma unroll
            for (int i = 0; i < 4; i++) {
                float a = As[ty*4 + i][k];
                acc[i][0] += a*wv.x; acc[i][1] += a*wv.y;
                acc[i][2] += a*wv.z; acc[i][3] += a*wv.w;
            }
        }
        __syncthreads();
    }
    int col = n0 + tx*4;
    float4 bv = *reinterpret_cast<const float4*>(bias + col);
    #pragma unroll
    for (int i = 0; i < 4; i++) {
        float4 o;
        o.x = acc[i][0] + bv.x; o.y = acc[i][1] + bv.y;
        o.z = acc[i][2] + bv.z; o.w = acc[i][3] + bv.w;
        *reinterpret_cast<float4*>(C + (r0 + ty*4 + i)*GG + col) = o;
    }
}

// ---------------- prep: E, fp16 transposed W2T/URt, cvec -------------------
__global__ void __launch_bounds__(512) prep_EF(
        const float* __restrict__ Wc, const float* __restrict__ Ww,
        const float* __restrict__ bc, const float* __restrict__ bw,
        const float* __restrict__ Uw, const float* __restrict__ Ur)
{
    __shared__ float st[DD], sb[DD], sc[DD];
    int d = blockIdx.x, j = threadIdx.x;
    if (j < DD) { st[j] = Wc[d*DD + j]; sb[j] = Wc[(DD + d)*DD + j]; sc[j] = bc[j]; }
    __syncthreads();
    float e = 0.f, f = 0.f, cv = 0.f;
    #pragma unroll 8
    for (int c = 0; c < DD; c++) {
        float w = Ww[c*GG + j];
        e += st[c]*w; f += sb[c]*w; cv += sc[c]*w;
    }
    g_E[d*GG + j] = e;
    int g = j >> 7, r = (j >> 5) & 3, jj = j & 31;
    int c = g*32 + jj;
    g_W2Th[(r*128 + c)*256 + d]       = __float2half(Uw[d*GG + j]);
    g_W2Th[(r*128 + c)*256 + 128 + d] = __float2half(f);
    g_URh [(r*128 + c)*128 + d]       = __float2half(Ur[d*GG + j]);
    if (d == 0) g_cvec[j] = cv + bw[j];
}

// ---------------- reader: cluster-4, d-split, fp16 smem Ur -----------------
#define R_UR  0        // [128 cols][128 k] half  (8192 floats)
#define R_XW  8192     // [128]
#define R_ZS  8320     // [128]
#define R_HB  8448     // [2][128]
#define R_MB  8704     // 2 bars
#define R_TOT 8708

__global__ void __launch_bounds__(512) __cluster_dims__(4, 1, 1)
reader_kernel()
{
    extern __shared__ __align__(16) float sm[];
    float* XWS = sm + R_XW;
    float* ZS  = sm + R_ZS;
    float* HB  = sm + R_HB;
    const uint2* URu = reinterpret_cast<const uint2*>(sm + R_UR);

    int tid = threadIdx.x, lane = tid & 31, warp = tid >> 5;
    uint32_t rank = ctarank();
    int b = blockIdx.x >> 2;

    uint32_t bar[2] = { smem_u32(sm + R_MB), smem_u32(sm + R_MB + 2) };
    if (tid == 0) { mbar_init(bar[0], 1); mbar_init(bar[1], 1); }

    {
        uint4* dst = reinterpret_cast<uint4*>(sm + R_UR);
        const uint4* src = reinterpret_cast<const uint4*>(g_URh) + (long)rank*2048;
        for (int i = tid; i < 2048; i += 512) dst[i] = src[i];
    }
    if (tid < 256) HB[tid] = 0.f;
    float cst = 0.f;
    __syncthreads();
    CLUSTER_SYNC_();

    uint32_t r_hb[2][4], r_bar[2][4];
    #pragma unroll
    for (int q = 0; q < 4; q++) {
        uint32_t pr = (rank + 1 + q) & 3;   // q=3 -> self
        r_bar[0][q] = mapa_u32(bar[0], pr);
        r_bar[1][q] = mapa_u32(bar[1], pr);
        r_hb[0][q]  = mapa_u32(smem_u32(HB), pr);
        r_hb[1][q]  = mapa_u32(smem_u32(HB + 128), pr);
    }

    const float* xwb = g_xw + (long)b*LL*GG;
    float* ob = g_oseq + (long)b*LL*DD;

    for (int t = 0; t < LL; t++) {
        int buf = t & 1, par = (t >> 1) & 1, prev = buf ^ 1;
        if (tid == 0) mbar_arrive_expect(bar[buf], 512);

        if (tid >= 256 && tid < 384) {
            int i = tid - 256;
            XWS[i] = xwb[t*GG + (i >> 5)*128 + rank*32 + (i & 31)];
        }
        {
            float4 hv = reinterpret_cast<const float4*>(HB + prev*128)[lane];
            float acc[8];
            #pragma unroll
            for (int i = 0; i < 8; i++)
                acc[i] = dot4_h(URu[(warp*8 + i)*32 + lane], hv);
            red8_store(acc, lane, ZS + warp*8);
        }
        __syncthreads();

        if (tid < 32) {
            int j = tid;
            float i_ = hsig (ZS[j]      + XWS[j]);
            float f_ = hsig (ZS[32 + j] + XWS[32 + j]);
            float g_ = tanh_fast(ZS[64 + j] + XWS[64 + j]);
            float o_ = hsig (ZS[96 + j] + XWS[96 + j]);
            cst = f_*cst + i_*g_;
            float h = o_ * tanh_fast(cst);
            float hn = __shfl_xor_sync(0xffffffffu, h, 1);
            if ((j & 1) == 0) {
                #pragma unroll
                for (int q = 0; q < 4; q++)
                    st_async_f64(r_hb[buf][q] + (rank*32u + (uint32_t)j)*4u, h, hn, r_bar[buf][q]);
            }
        }
        mbar_wait(bar[buf], par);
        if (rank == 0 && tid < 128) ob[t*DD + tid] = HB[buf*128 + tid];
    }
    CLUSTER_SYNC_();
}

__global__ void nop_kernel() {}

// ---------------- writer: cluster-4, latency-hidden h exchange -------------
#define W_W    0        // [128 cols][256 k] half (16384 floats)
#define W_MEM  16384    // [64][128]              (8192)
#define W_PA   24576    // [16][128]              (2048)
#define W_MRTB 26624    // [4][128]               (512)
#define W_PRE  27136    // [128]
#define W_ONX  27264    // [128]
#define W_ZS   27392    // [128]
#define W_HB   27520    // [2][128]
#define W_MRT  27776    // [128]
#define W_ZZ   27904    // [64]
#define W_EE   27968    // [64]
#define W_SB   28032    // [4]
#define W_HOB  28036    // [4] h.o partial box
#define W_MB   28040    // 3 bars (6 floats); 28040*4 % 8 == 0
#define W_TOT  28046

__global__ void __launch_bounds__(512) __cluster_dims__(4, 1, 1)
writer_kernel(const float* __restrict__ x, float* __restrict__ out)
{
    extern __shared__ __align__(16) float sm[];
    float* MEM  = sm + W_MEM;
    float* PA   = sm + W_PA;
    float* MRTB = sm + W_MRTB;
    float* PRE  = sm + W_PRE;
    float* ONX  = sm + W_ONX;
    float* ZS   = sm + W_ZS;
    float* HB   = sm + W_HB;
    float* MRT  = sm + W_MRT;
    float* ZZ   = sm + W_ZZ;
    float* EE   = sm + W_EE;
    float* SB   = sm + W_SB;
    float* HOB  = sm + W_HOB;
    const uint2* W2u = reinterpret_cast<const uint2*>(sm + W_W);

    int tid = threadIdx.x, lane = tid & 31, warp = tid >> 5;
    uint32_t rank = ctarank();
    int b = blockIdx.x >> 2;

    uint32_t mrt_bar = smem_u32(sm + W_MB);
    uint32_t hbar[2] = { smem_u32(sm + W_MB + 2), smem_u32(sm + W_MB + 4) };
    if (tid == 0) { mbar_init(mrt_bar, 1); mbar_init(hbar[0], 1); mbar_init(hbar[1], 1); }

    const float* obq  = g_oseq + (long)b*LL*DD;
    const float* preb = g_pre  + (long)b*LL*GG;

    {
        uint4* dst = reinterpret_cast<uint4*>(sm + W_W);
        const uint4* src = reinterpret_cast<const uint4*>(g_W2Th) + (long)rank*4096;
        for (int i = tid; i < 4096; i += 512) dst[i] = src[i];
    }
    {
        const float* xb = x + ((long)b*LL + rank*64)*DD;
        for (int i = tid; i < 64*DD; i += 512) MEM[i] = xb[i];
    }
    if (tid < 256) HB[tid] = 0.f;
    if (tid < 128) ONX[tid] = obq[tid];
    if (tid < 64)  ZZ[tid] = 0.f;
    float cst = 0.f;
    __syncthreads();
    CLUSTER_SYNC_();

    uint32_t r_mrtb[4], r_sb[4], r_mbar[4];
    #pragma unroll
    for (int q = 0; q < 4; q++) {
        uint32_t pr = (rank + 1 + q) & 3;   // q=3 -> self
        r_mrtb[q] = mapa_u32(smem_u32(MRTB), pr);
        r_sb[q]   = mapa_u32(smem_u32(SB), pr);
        r_mbar[q] = mapa_u32(mrt_bar, pr);
    }
    uint32_t r_hb[2][4], r_hbar[2][4], r_hob[4];
    #pragma unroll
    for (int q = 0; q < 4; q++) {
        uint32_t pr = (rank + 1 + q) & 3;
        r_hbar[0][q] = mapa_u32(hbar[0], pr);
        r_hbar[1][q] = mapa_u32(hbar[1], pr);
        r_hb[0][q]   = mapa_u32(smem_u32(HB), pr);
        r_hb[1][q]   = mapa_u32(smem_u32(HB + 128), pr);
        r_hob[q]     = mapa_u32(smem_u32(HOB), pr);
    }

    float4* MEM4 = reinterpret_cast<float4*>(MEM);
    float4* PA4  = reinterpret_cast<float4*>(PA);
    const float2* PA2 = reinterpret_cast<const float2*>(PA);
    const float4* ONX4 = reinterpret_cast<const float4*>(ONX);
    const float4* MRT4 = reinterpret_cast<const float4*>(MRT);

    // ---- initial pass: h=0, z=0 -> scores o_0 . mem, EE, PA ---------------
    {
        float4 ov = ONX4[lane];
        int r0 = warp*4;
        float4 m[4]; float pr_[4];
        #pragma unroll
        for (int li = 0; li < 4; li++) {
            m[li] = MEM4[(r0 + li)*32 + lane];
            pr_[li] = m[li].x*ov.x + m[li].y*ov.y + m[li].z*ov.z + m[li].w*ov.w;
        }
        #pragma unroll
        for (int ofs = 16, n = 4; ofs >= 8; ofs >>= 1, n >>= 1) {
            int half = n >> 1;
            bool side = (lane & ofs) != 0;
            #pragma unroll
            for (int i = 0; i < 2; i++) {
                if (i < half) {
                    float send = side ? pr_[i] : pr_[i + half];
                    float recv = __shfl_xor_sync(0xffffffffu, send, ofs);
                    pr_[i] = (side ? pr_[i + half] : pr_[i]) + recv;
                }
            }
        }
        pr_[0] += __shfl_xor_sync(0xffffffffu, pr_[0], 4);
        pr_[0] += __shfl_xor_sync(0xffffffffu, pr_[0], 2);
        pr_[0] += __shfl_xor_sync(0xffffffffu, pr_[0], 1);
        if ((lane & 7) == 0) EE[r0 + ((lane >> 3) & 3)] = __expf(pr_[0]);
        __syncwarp();
        float4 pacc = make_float4(0.f, 0.f, 0.f, 0.f);
        #pragma unroll
        for (int li = 0; li < 4; li++) {
            float e = EE[r0 + li];
            pacc.x = fmaf(e, m[li].x, pacc.x);
            pacc.y = fmaf(e, m[li].y, pacc.y);
            pacc.z = fmaf(e, m[li].z, pacc.z);
            pacc.w = fmaf(e, m[li].w, pacc.w);
        }
        PA4[warp*32 + lane] = pacc;
    }
    __syncthreads();

    for (int t = 0; t < LL; t++) {
        int bufh = t & 1, parh = (t >> 1) & 1, parm = t & 1, prevh = bufh ^ 1;
        if (tid == 0) {
            mbar_arrive_expect(mrt_bar, 2064);       // 4 x (512 + 4)
            mbar_arrive_expect(hbar[bufh], 528);     // 4 x (128 + 4)
        }
        // ---- phase1: p/S reduce + send (incl self); PRE + ONX prefetch
        if (tid < 64) {
            float2 p = make_float2(0.f, 0.f);
            #pragma unroll
            for (int w = 0; w < 16; w++) {
                float2 v = PA2[w*64 + tid];
                p.x += v.x; p.y += v.y;
            }
            #pragma unroll
            for (int q = 0; q < 4; q++)
                st_async_f64(r_mrtb[q] + (rank*128u + 2u*(uint32_t)tid)*4u, p.x, p.y, r_mbar[q]);
        } else if (tid < 96) {
            float v = EE[lane] + EE[32 + lane];
            #pragma unroll
            for (int o = 16; o > 0; o >>= 1) v += __shfl_xor_sync(0xffffffffu, v, o);
            if (lane == 0) {
                #pragma unroll
                for (int q = 0; q < 4; q++)
                    st_async_f32(r_sb[q] + rank*4u, v, r_mbar[q]);
            }
        } else if (tid >= 160 && tid < 288) {
            int i = tid - 160;
            PRE[i] = preb[t*GG + (i >> 5)*128 + rank*32 + (i & 31)];
        } else if (tid >= 288 && tid < 416) {
            int i = tid - 288;
            int tn = (t + 1 < LL) ? t + 1 : LL - 1;
            ONX[i] = obq[tn*DD + i];
        }
        // Uw-half GEMV (all threads) fills the mrt round trip
        float acc[8];
        {
            float4 hv = reinterpret_cast<const float4*>(HB + prevh*128)[lane];
            #pragma unroll
            for (int i = 0; i < 8; i++)
                acc[i] = dot4_h(W2u[(warp*8 + i)*64 + lane], hv);
        }

        // ---- phase2: m_rt combine + ZZ
        mbar_wait(mrt_bar, parm);
        if (tid < 128) {
            float inv = 1.0f / (SB[0] + SB[1] + SB[2] + SB[3]);
            MRT[tid] = (MRTB[tid] + MRTB[128 + tid] + MRTB[256 + tid] + MRTB[384 + tid]) * inv;
        } else if (tid < 192) {
            float inv = 1.0f / (SB[0] + SB[1] + SB[2] + SB[3]);
            ZZ[tid - 128] = EE[tid - 128] * inv;
        }
        __syncthreads();                              // B

        // ---- phase3: F-half GEMV + batched reduce -> ZS
        {
            float4 mv = MRT4[lane];
            #pragma unroll
            for (int i = 0; i < 8; i++)
                acc[i] += dot4_h(W2u[(warp*8 + i)*64 + 32 + lane], mv);
            red8_store(acc, lane, ZS + warp*8);
        }
        __syncthreads();                              // C

        // ---- phase4 (warp0 only): gates + h/ho send (incl self)
        if (warp == 0) {
            int j = lane;
            float i_ = hsig (ZS[j]      + PRE[j]);
            float f_ = hsig (ZS[32 + j] + PRE[32 + j]);
            float g_ = tanh_fast(ZS[64 + j] + PRE[64 + j]);
            float o_ = hsig (ZS[96 + j] + PRE[96 + j]);
            cst = f_*cst + i_*g_;
            float h = o_ * tanh_fast(cst);
            if (t == LL - 1) out[b*DD + rank*32 + j] = h;
            float hop = h * ONX[rank*32 + j];
            #pragma unroll
            for (int o = 16; o > 0; o >>= 1) hop += __shfl_xor_sync(0xffffffffu, hop, o);
            float hn = __shfl_xor_sync(0xffffffffu, h, 1);
            if ((j & 1) == 0) {
                #pragma unroll
                for (int q = 0; q < 4; q++)
                    st_async_f64(r_hb[bufh][q] + (rank*32u + (uint32_t)j)*4u, h, hn, r_hbar[bufh][q]);
            }
            if (j == 0) {
                #pragma unroll
                for (int q = 0; q < 4; q++)
                    st_async_f32(r_hob[q] + rank*4u, hop, r_hbar[bufh][q]);
            }
        }

        // ---- phase5a (all warps, h still in flight): old-mem score dots
        float4 ov = ONX4[lane];
        int r0 = warp*4;
        float4 m[4]; float dd[4];
        #pragma unroll
        for (int li = 0; li < 4; li++) {
            m[li] = MEM4[(r0 + li)*32 + lane];
            dd[li] = m[li].x*ov.x + m[li].y*ov.y + m[li].z*ov.z + m[li].w*ov.w;
        }
        #pragma unroll
        for (int ofs = 16, n = 4; ofs >= 8; ofs >>= 1, n >>= 1) {
            int half = n >> 1;
            bool side = (lane & ofs) != 0;
            #pragma unroll
            for (int i = 0; i < 2; i++) {
                if (i < half) {
                    float send = side ? dd[i] : dd[i + half];
                    float recv = __shfl_xor_sync(0xffffffffu, send, ofs);
                    dd[i] = (side ? dd[i + half] : dd[i]) + recv;
                }
            }
        }
        dd[0] += __shfl_xor_sync(0xffffffffu, dd[0], 4);
        dd[0] += __shfl_xor_sync(0xffffffffu, dd[0], 2);
        dd[0] += __shfl_xor_sync(0xffffffffu, dd[0], 1);

        mbar_wait(hbar[bufh], parh);

        // ---- phase5b: s = (1-z)d + z(h.o); e; mem writeback; PA partials
        float ho = HOB[0] + HOB[1] + HOB[2] + HOB[3];
        if ((lane & 7) == 0) {
            int row = r0 + ((lane >> 3) & 3);
            float z = ZZ[row];
            EE[row] = __expf(dd[0] + z*(ho - dd[0]));
        }
        __syncwarp();
        {
            float4 hv = reinterpret_cast<const float4*>(HB + bufh*128)[lane];
            float4 pacc = make_float4(0.f, 0.f, 0.f, 0.f);
            float u = 0.f;
            #pragma unroll
            for (int li = 0; li < 4; li++) {
                int l = r0 + li;
                float e = EE[l], z = ZZ[l];
                float w = e - e*z;           // e(1-z)
                pacc.x = fmaf(w, m[li].x, pacc.x);
                pacc.y = fmaf(w, m[li].y, pacc.y);
                pacc.z = fmaf(w, m[li].z, pacc.z);
                pacc.w = fmaf(w, m[li].w, pacc.w);
                u += e*z;
                float4 mm = m[li];
                mm.x = fmaf(z, hv.x - mm.x, mm.x);
                mm.y = fmaf(z, hv.y - mm.y, mm.y);
                mm.z = fmaf(z, hv.z - mm.z, mm.z);
                mm.w = fmaf(z, hv.w - mm.w, mm.w);
                MEM4[l*32 + lane] = mm;
            }
            pacc.x = fmaf(u, hv.x, pacc.x);
            pacc.y = fmaf(u, hv.y, pacc.y);
            pacc.z = fmaf(u, hv.z, pacc.z);
            pacc.w = fmaf(u, hv.w, pacc.w);
            PA4[warp*32 + lane] = pacc;
        }
        __syncthreads();                              // F
    }
    CLUSTER_SYNC_();
}

// ---------------------------------------------------------------------------
extern "C" void kernel_launch(void* const* d_in, const int* in_sizes, int n_in,
                              void* d_out, int out_size)
{
    const float* x  = (const float*)d_in[0];
    const float* Wr = (const float*)d_in[1];
    const float* Ur = (const float*)d_in[2];
    const float* br = (const float*)d_in[3];
    const float* Ww = (const float*)d_in[4];
    const float* Uw = (const float*)d_in[5];
    const float* bw = (const float*)d_in[6];
    const float* Wc = (const float*)d_in[7];
    const float* bc = (const float*)d_in[8];
    float* out = (float*)d_out;
    (void)in_sizes; (void)n_in; (void)out_size;

    void *p_xw, *p_pre, *p_oseq, *p_E, *p_cvec;
    cudaGetSymbolAddress(&p_xw,   g_xw);
    cudaGetSymbolAddress(&p_pre,  g_pre);
    cudaGetSymbolAddress(&p_oseq, g_oseq);
    cudaGetSymbolAddress(&p_E,    g_E);
    cudaGetSymbolAddress(&p_cvec, g_cvec);

    cudaFuncSetAttribute(reader_kernel,
                         cudaFuncAttributeMaxDynamicSharedMemorySize,
                         R_TOT * (int)sizeof(float));
    cudaFuncSetAttribute(writer_kernel,
                         cudaFuncAttributeMaxDynamicSharedMemorySize,
                         W_TOT * (int)sizeof(float));

    dim3 gdim(GG/64, (BB*LL)/64);

    gemm_k128_n512<<<gdim, 256>>>(x, Wr, br, (float*)p_xw);
    prep_EF<<<DD, 512>>>(Wc, Ww, bc, bw, Uw, Ur);
    reader_kernel<<<4*BB, 512, R_TOT * (int)sizeof(float)>>>();
    gemm_k128_n512<<<gdim, 256>>>((const float*)p_oseq, (const float*)p_E,
                                  (const float*)p_cvec, (float*)p_pre);
    nop_kernel<<<1, 32>>>();
    writer_kernel<<<4*BB, 512, W_TOT * (int)sizeof(float)>>>(x, out);
}

// round 12
// speedup vs baseline: 1.6005x; 1.6005x over previous
#include <cuda_runtime.h>
#include <cuda_fp16.h>
#include <math.h>
#include <stdint.h>

#define BB 32
#define LL 256
#define DD 128
#define GG 512

__device__ float g_xw  [BB*LL*GG];
__device__ float g_pre [BB*LL*GG];
__device__ float g_oseq[BB*LL*DD];
__device__ float g_E   [DD*GG];
// fp16, transposed, rank-sliced, gate-permuted recurrent weights:
// g_W2Th[r][c][k], c = g*32 + jj (global col = g*128 + r*32 + jj), k: 0..127 Uw, 128..255 F
__device__ __align__(16) __half g_W2Th[4*128*256];
__device__ __align__(16) __half g_URh [4*128*128];
__device__ float g_cvec[GG];

__device__ __forceinline__ float hsig(float x) {
    return fminf(fmaxf(0.2f*x + 0.5f, 0.0f), 1.0f);
}
// fast tanh via MUFU exp: max err ~1e-6, saturates correctly at both ends
__device__ __forceinline__ float tanh_fast(float x) {
    float e = __expf(fminf(2.0f*x, 80.0f));
    return 1.0f - __fdividef(2.0f, e + 1.0f);
}
__device__ __forceinline__ uint32_t smem_u32(const void* p) {
    uint32_t a;
    asm("{ .reg .u64 t; cvta.to.shared.u64 t, %1; cvt.u32.u64 %0, t; }" : "=r"(a) : "l"(p));
    return a;
}
__device__ __forceinline__ uint32_t ctarank() {
    uint32_t r; asm("mov.u32 %0, %%cluster_ctarank;" : "=r"(r)); return r;
}
__device__ __forceinline__ uint32_t mapa_u32(uint32_t a, uint32_t rk) {
    uint32_t o; asm("mapa.shared::cluster.u32 %0, %1, %2;" : "=r"(o) : "r"(a), "r"(rk)); return o;
}
__device__ __forceinline__ void mbar_init(uint32_t a, uint32_t cnt) {
    asm volatile("mbarrier.init.shared.b64 [%0], %1;" :: "r"(a), "r"(cnt) : "memory");
}
__device__ __forceinline__ void mbar_arrive_expect(uint32_t a, uint32_t tx) {
    asm volatile("mbarrier.arrive.expect_tx.shared.b64 _, [%0], %1;" :: "r"(a), "r"(tx) : "memory");
}
__device__ __forceinline__ void mbar_wait(uint32_t a, uint32_t parity) {
    uint32_t done;
    asm volatile("{\n\t.reg .pred p;\n\t"
        "mbarrier.try_wait.parity.acquire.cta.shared::cta.b64 p, [%1], %2;\n\t"
        "selp.b32 %0, 1, 0, p;\n\t}" : "=r"(done) : "r"(a), "r"(parity) : "memory");
    if (!done) {
        asm volatile("{\n\t.reg .pred P1;\n\tWL_%=:\n\t"
            "mbarrier.try_wait.parity.acquire.cta.shared::cta.b64 P1, [%0], %1, 0x989680;\n\t"
            "@P1 bra.uni WD_%=;\n\tbra.uni WL_%=;\n\tWD_%=:\n\t}"
            :: "r"(a), "r"(parity) : "memory");
    }
}
__device__ __forceinline__ void st_async_f32(uint32_t ra, float v, uint32_t rmb) {
    asm volatile("st.async.shared::cluster.mbarrier::complete_tx::bytes.b32 [%0], %1, [%2];"
                 :: "r"(ra), "r"(__float_as_uint(v)), "r"(rmb) : "memory");
}
__device__ __forceinline__ void st_async_f64(uint32_t ra, float a, float b, uint32_t rmb) {
    unsigned long long v = ((unsigned long long)__float_as_uint(b) << 32) | __float_as_uint(a);
    asm volatile("st.async.shared::cluster.mbarrier::complete_tx::bytes.b64 [%0], %1, [%2];"
                 :: "r"(ra), "l"(v), "r"(rmb) : "memory");
}
#define CLUSTER_SYNC_() do { \
    asm volatile("barrier.cluster.arrive.aligned;" ::: "memory"); \
    asm volatile("barrier.cluster.wait.aligned;" ::: "memory"); } while (0)

// batched reduce of 8 per-lane col-partials -> dst[0..7] full sums
__device__ __forceinline__ void red8_store(float* p, int lane, float* dst) {
    #pragma unroll
    for (int ofs = 16, n = 8; ofs >= 4; ofs >>= 1, n >>= 1) {
        int half = n >> 1;
        bool side = (lane & ofs) != 0;
        #pragma unroll
        for (int i = 0; i < 4; i++) {
            if (i < half) {
                float send = side ? p[i] : p[i + half];
                float recv = __shfl_xor_sync(0xffffffffu, send, ofs);
                p[i] = (side ? p[i + half] : p[i]) + recv;
            }
        }
    }
    p[0] += __shfl_xor_sync(0xffffffffu, p[0], 2);
    p[0] += __shfl_xor_sync(0xffffffffu, p[0], 1);
    if ((lane & 3) == 0) dst[(lane >> 2) & 7] = p[0];
}

// fp16 GEMV inner
__device__ __forceinline__ float dot4_h(uint2 w, float4 hv) {
    float2 a = __half22float2(*reinterpret_cast<__half2*>(&w.x));
    float2 b = __half22float2(*reinterpret_cast<__half2*>(&w.y));
    return hv.x*a.x + hv.y*a.y + hv.z*b.x + hv.w*b.y;
}

// ---------------- GEMM: C[M,512] = A[M,128] @ W[128,512] + bias ------------
__global__ void __launch_bounds__(256) gemm_k128_n512(
        const float* __restrict__ A, const float* __restrict__ W,
        const float* __restrict__ bias, float* __restrict__ C)
{
    __shared__ __align__(16) float As[64][68];
    __shared__ __align__(16) float Ws[64][64];
    int tid = threadIdx.x, tx = tid & 15, ty = tid >> 4;
    int n0 = blockIdx.x * 64;
    long r0 = (long)blockIdx.y * 64;
    float acc[4][4] = {};
    for (int kc = 0; kc < 128; kc += 64) {
        #pragma unroll
        for (int i = 0; i < 4; i++) {
            int f = tid + i*256, row = f >> 4, c4 = (f & 15) * 4;
            *reinterpret_cast<float4*>(&As[row][c4]) =
                *reinterpret_cast<const float4*>(A + (r0 + row)*128 + kc + c4);
            *reinterpret_cast<float4*>(&Ws[row][c4]) =
                *reinterpret_cast<const float4*>(W + (long)(kc + row)*GG + n0 + c4);
        }
        __syncthreads();
        #pragma unroll
        for (int k = 0; k < 64; k++) {
            float4 wv = *reinterpret_cast<const float4*>(&Ws[k][tx*4]);
            #pragma unroll
            for (int i = 0; i < 4; i++) {
                float a = As[ty*4 + i][k];
                acc[i][0] += a*wv.x; acc[i][1] += a*wv.y;
                acc[i][2] += a*wv.z; acc[i][3] += a*wv.w;
            }
        }
        __syncthreads();
    }
    int col = n0 + tx*4;
    float4 bv = *reinterpret_cast<const float4*>(bias + col);
    #pragma unroll
    for (int i = 0; i < 4; i++) {
        float4 o;
        o.x = acc[i][0] + bv.x; o.y = acc[i][1] + bv.y;
        o.z = acc[i][2] + bv.z; o.w = acc[i][3] + bv.w;
        *reinterpret_cast<float4*>(C + (r0 + ty*4 + i)*GG + col) = o;
    }
}

// ---------------- prep: E, fp16 transposed W2T/URt, cvec -------------------
__global__ void __launch_bounds__(512) prep_EF(
        const float* __restrict__ Wc, const float* __restrict__ Ww,
        const float* __restrict__ bc, const float* __restrict__ bw,
        const float* __restrict__ Uw, const float* __restrict__ Ur)
{
    __shared__ float st[DD], sb[DD], sc[DD];
    int d = blockIdx.x, j = threadIdx.x;
    if (j < DD) { st[j] = Wc[d*DD + j]; sb[j] = Wc[(DD + d)*DD + j]; sc[j] = bc[j]; }
    __syncthreads();
    float e = 0.f, f = 0.f, cv = 0.f;
    #pragma unroll 8
    for (int c = 0; c < DD; c++) {
        float w = Ww[c*GG + j];
        e += st[c]*w; f += sb[c]*w; cv += sc[c]*w;
    }
    g_E[d*GG + j] = e;
    int g = j >> 7, r = (j >> 5) & 3, jj = j & 31;
    int c = g*32 + jj;
    g_W2Th[(r*128 + c)*256 + d]       = __float2half(Uw[d*GG + j]);
    g_W2Th[(r*128 + c)*256 + 128 + d] = __float2half(f);
    g_URh [(r*128 + c)*128 + d]       = __float2half(Ur[d*GG + j]);
    if (d == 0) g_cvec[j] = cv + bw[j];
}

// ---------------- reader: cluster-4, d-split, fp16 smem Ur -----------------
#define R_UR  0        // [128 cols][128 k] half  (8192 floats)
#define R_XW  8192     // [128]
#define R_ZS  8320     // [128]
#define R_HB  8448     // [2][128]
#define R_MB  8704     // 2 bars
#define R_TOT 8708

__global__ void __launch_bounds__(512) __cluster_dims__(4, 1, 1)
reader_kernel()
{
    extern __shared__ __align__(16) float sm[];
    float* XWS = sm + R_XW;
    float* ZS  = sm + R_ZS;
    float* HB  = sm + R_HB;
    const uint2* URu = reinterpret_cast<const uint2*>(sm + R_UR);

    int tid = threadIdx.x, lane = tid & 31, warp = tid >> 5;
    uint32_t rank = ctarank();
    int b = blockIdx.x >> 2;

    uint32_t bar[2] = { smem_u32(sm + R_MB), smem_u32(sm + R_MB + 2) };
    if (tid == 0) { mbar_init(bar[0], 1); mbar_init(bar[1], 1); }

    {
        uint4* dst = reinterpret_cast<uint4*>(sm + R_UR);
        const uint4* src = reinterpret_cast<const uint4*>(g_URh) + (long)rank*2048;
        for (int i = tid; i < 2048; i += 512) dst[i] = src[i];
    }
    if (tid < 256) HB[tid] = 0.f;
    float cst = 0.f;
    __syncthreads();
    CLUSTER_SYNC_();

    uint32_t r_hb[2][4], r_bar[2][4];
    #pragma unroll
    for (int q = 0; q < 4; q++) {
        uint32_t pr = (rank + 1 + q) & 3;   // q=3 -> self
        r_bar[0][q] = mapa_u32(bar[0], pr);
        r_bar[1][q] = mapa_u32(bar[1], pr);
        r_hb[0][q]  = mapa_u32(smem_u32(HB), pr);
        r_hb[1][q]  = mapa_u32(smem_u32(HB + 128), pr);
    }

    const float* xwb = g_xw + (long)b*LL*GG;
    float* ob = g_oseq + (long)b*LL*DD;

    for (int t = 0; t < LL; t++) {
        int buf = t & 1, par = (t >> 1) & 1, prev = buf ^ 1;
        if (tid == 0) mbar_arrive_expect(bar[buf], 512);

        if (tid >= 256 && tid < 384) {
            int i = tid - 256;
            XWS[i] = xwb[t*GG + (i >> 5)*128 + rank*32 + (i & 31)];
        }
        {
            float4 hv = reinterpret_cast<const float4*>(HB + prev*128)[lane];
            float acc[8];
            #pragma unroll
            for (int i = 0; i < 8; i++)
                acc[i] = dot4_h(URu[(warp*8 + i)*32 + lane], hv);
            red8_store(acc, lane, ZS + warp*8);
        }
        __syncthreads();

        if (tid < 32) {
            int j = tid;
            float i_ = hsig (ZS[j]      + XWS[j]);
            float f_ = hsig (ZS[32 + j] + XWS[32 + j]);
            float g_ = tanh_fast(ZS[64 + j] + XWS[64 + j]);
            float o_ = hsig (ZS[96 + j] + XWS[96 + j]);
            cst = f_*cst + i_*g_;
            float h = o_ * tanh_fast(cst);
            float hn = __shfl_xor_sync(0xffffffffu, h, 1);
            if ((j & 1) == 0) {
                #pragma unroll
                for (int q = 0; q < 4; q++)
                    st_async_f64(r_hb[buf][q] + (rank*32u + (uint32_t)j)*4u, h, hn, r_bar[buf][q]);
            }
        }
        mbar_wait(bar[buf], par);
        if (rank == 0 && tid < 128) ob[t*DD + tid] = HB[buf*128 + tid];
    }
    CLUSTER_SYNC_();
}

__global__ void nop_kernel() {}

// ---------------- writer: cluster-4, latency-hidden h exchange -------------
#define W_W    0        // [128 cols][256 k] half (16384 floats)
#define W_MEM  16384    // [64][128]              (8192)
#define W_PA   24576    // [16][128]              (2048)
#define W_MRTB 26624    // [4][128]               (512)
#define W_PRE  27136    // [128]
#define W_ONX  27264    // [128]
#define W_ZS   27392    // [128]
#define W_HB   27520    // [2][128]
#define W_MRT  27776    // [128]
#define W_ZZ   27904    // [64]
#define W_EE   27968    // [64]
#define W_SB   28032    // [4]
#define W_HOB  28036    // [4] h.o partial box
#define W_MB   28040    // 3 bars (6 floats); 28040*4 % 8 == 0
#define W_TOT  28046

__global__ void __launch_bounds__(512) __cluster_dims__(4, 1, 1)
writer_kernel(const float* __restrict__ x, float* __restrict__ out)
{
    extern __shared__ __align__(16) float sm[];
    float* MEM  = sm + W_MEM;
    float* PA   = sm + W_PA;
    float* MRTB = sm + W_MRTB;
    float* PRE  = sm + W_PRE;
    float* ONX  = sm + W_ONX;
    float* ZS   = sm + W_ZS;
    float* HB   = sm + W_HB;
    float* MRT  = sm + W_MRT;
    float* ZZ   = sm + W_ZZ;
    float* EE   = sm + W_EE;
    float* SB   = sm + W_SB;
    float* HOB  = sm + W_HOB;
    const uint2* W2u = reinterpret_cast<const uint2*>(sm + W_W);

    int tid = threadIdx.x, lane = tid & 31, warp = tid >> 5;
    uint32_t rank = ctarank();
    int b = blockIdx.x >> 2;

    uint32_t mrt_bar = smem_u32(sm + W_MB);
    uint32_t hbar[2] = { smem_u32(sm + W_MB + 2), smem_u32(sm + W_MB + 4) };
    if (tid == 0) { mbar_init(mrt_bar, 1); mbar_init(hbar[0], 1); mbar_init(hbar[1], 1); }

    const float* obq  = g_oseq + (long)b*LL*DD;
    const float* preb = g_pre  + (long)b*LL*GG;

    {
        uint4* dst = reinterpret_cast<uint4*>(sm + W_W);
        const uint4* src = reinterpret_cast<const uint4*>(g_W2Th) + (long)rank*4096;
        for (int i = tid; i < 4096; i += 512) dst[i] = src[i];
    }
    {
        const float* xb = x + ((long)b*LL + rank*64)*DD;
        for (int i = tid; i < 64*DD; i += 512) MEM[i] = xb[i];
    }
    if (tid < 256) HB[tid] = 0.f;
    if (tid < 128) ONX[tid] = obq[tid];
    if (tid < 64)  ZZ[tid] = 0.f;
    float cst = 0.f;
    __syncthreads();
    CLUSTER_SYNC_();

    uint32_t r_mrtb[4], r_sb[4], r_mbar[4];
    #pragma unroll
    for (int q = 0; q < 4; q++) {
        uint32_t pr = (rank + 1 + q) & 3;   // q=3 -> self
        r_mrtb[q] = mapa_u32(smem_u32(MRTB), pr);
        r_sb[q]   = mapa_u32(smem_u32(SB), pr);
        r_mbar[q] = mapa_u32(mrt_bar, pr);
    }
    uint32_t r_hb[2][4], r_hbar[2][4], r_hob[4];
    #pragma unroll
    for (int q = 0; q < 4; q++) {
        uint32_t pr = (rank + 1 + q) & 3;
        r_hbar[0][q] = mapa_u32(hbar[0], pr);
        r_hbar[1][q] = mapa_u32(hbar[1], pr);
        r_hb[0][q]   = mapa_u32(smem_u32(HB), pr);
        r_hb[1][q]   = mapa_u32(smem_u32(HB + 128), pr);
        r_hob[q]     = mapa_u32(smem_u32(HOB), pr);
    }

    float4* MEM4 = reinterpret_cast<float4*>(MEM);
    float4* PA4  = reinterpret_cast<float4*>(PA);
    const float2* PA2 = reinterpret_cast<const float2*>(PA);
    const float4* ONX4 = reinterpret_cast<const float4*>(ONX);
    const float4* MRT4 = reinterpret_cast<const float4*>(MRT);

    // ---- initial pass: h=0, z=0 -> scores o_0 . mem, EE, PA ---------------
    {
        float4 ov = ONX4[lane];
        int r0 = warp*4;
        float4 m[4]; float pr_[4];
        #pragma unroll
        for (int li = 0; li < 4; li++) {
            m[li] = MEM4[(r0 + li)*32 + lane];
            pr_[li] = m[li].x*ov.x + m[li].y*ov.y + m[li].z*ov.z + m[li].w*ov.w;
        }
        #pragma unroll
        for (int ofs = 16, n = 4; ofs >= 8; ofs >>= 1, n >>= 1) {
            int half = n >> 1;
            bool side = (lane & ofs) != 0;
            #pragma unroll
            for (int i = 0; i < 2; i++) {
                if (i < half) {
                    float send = side ? pr_[i] : pr_[i + half];
                    float recv = __shfl_xor_sync(0xffffffffu, send, ofs);
                    pr_[i] = (side ? pr_[i + half] : pr_[i]) + recv;
                }
            }
        }
        pr_[0] += __shfl_xor_sync(0xffffffffu, pr_[0], 4);
        pr_[0] += __shfl_xor_sync(0xffffffffu, pr_[0], 2);
        pr_[0] += __shfl_xor_sync(0xffffffffu, pr_[0], 1);
        if ((lane & 7) == 0) EE[r0 + ((lane >> 3) & 3)] = __expf(pr_[0]);
        __syncwarp();
        float4 pacc = make_float4(0.f, 0.f, 0.f, 0.f);
        #pragma unroll
        for (int li = 0; li < 4; li++) {
            float e = EE[r0 + li];
            pacc.x = fmaf(e, m[li].x, pacc.x);
            pacc.y = fmaf(e, m[li].y, pacc.y);
            pacc.z = fmaf(e, m[li].z, pacc.z);
            pacc.w = fmaf(e, m[li].w, pacc.w);
        }
        PA4[warp*32 + lane] = pacc;
    }
    __syncthreads();

    for (int t = 0; t < LL; t++) {
        int bufh = t & 1, parh = (t >> 1) & 1, parm = t & 1, prevh = bufh ^ 1;
        if (tid == 0) {
            mbar_arrive_expect(mrt_bar, 2064);       // 4 x (512 + 4)
            mbar_arrive_expect(hbar[bufh], 528);     // 4 x (128 + 4)
        }
        // ---- phase1: p/S reduce + send (incl self); PRE + ONX prefetch
        if (tid < 64) {
            float2 p = make_float2(0.f, 0.f);
            #pragma unroll
            for (int w = 0; w < 16; w++) {
                float2 v = PA2[w*64 + tid];
                p.x += v.x; p.y += v.y;
            }
            #pragma unroll
            for (int q = 0; q < 4; q++)
                st_async_f64(r_mrtb[q] + (rank*128u + 2u*(uint32_t)tid)*4u, p.x, p.y, r_mbar[q]);
        } else if (tid < 96) {
            float v = EE[lane] + EE[32 + lane];
            #pragma unroll
            for (int o = 16; o > 0; o >>= 1) v += __shfl_xor_sync(0xffffffffu, v, o);
            if (lane == 0) {
                #pragma unroll
                for (int q = 0; q < 4; q++)
                    st_async_f32(r_sb[q] + rank*4u, v, r_mbar[q]);
            }
        } else if (tid >= 160 && tid < 288) {
            int i = tid - 160;
            PRE[i] = preb[t*GG + (i >> 5)*128 + rank*32 + (i & 31)];
        } else if (tid >= 288 && tid < 416) {
            int i = tid - 288;
            int tn = (t + 1 < LL) ? t + 1 : LL - 1;
            ONX[i] = obq[tn*DD + i];
        }
        // Uw-half GEMV (all threads) fills the mrt round trip
        float acc[8];
        {
            float4 hv = reinterpret_cast<const float4*>(HB + prevh*128)[lane];
            #pragma unroll
            for (int i = 0; i < 8; i++)
                acc[i] = dot4_h(W2u[(warp*8 + i)*64 + lane], hv);
        }

        // ---- phase2: m_rt combine + ZZ
        mbar_wait(mrt_bar, parm);
        if (tid < 128) {
            float inv = 1.0f / (SB[0] + SB[1] + SB[2] + SB[3]);
            MRT[tid] = (MRTB[tid] + MRTB[128 + tid] + MRTB[256 + tid] + MRTB[384 + tid]) * inv;
        } else if (tid < 192) {
            float inv = 1.0f / (SB[0] + SB[1] + SB[2] + SB[3]);
            ZZ[tid - 128] = EE[tid - 128] * inv;
        }
        __syncthreads();                              // B

        // ---- phase3: F-half GEMV + batched reduce -> ZS
        {
            float4 mv = MRT4[lane];
            #pragma unroll
            for (int i = 0; i < 8; i++)
                acc[i] += dot4_h(W2u[(warp*8 + i)*64 + 32 + lane], mv);
            red8_store(acc, lane, ZS + warp*8);
        }
        __syncthreads();                              // C

        // ---- phase4 (warp0 only): gates + h/ho send (incl self)
        if (warp == 0) {
            int j = lane;
            float i_ = hsig (ZS[j]      + PRE[j]);
            float f_ = hsig (ZS[32 + j] + PRE[32 + j]);
            float g_ = tanh_fast(ZS[64 + j] + PRE[64 + j]);
            float o_ = hsig (ZS[96 + j] + PRE[96 + j]);
            cst = f_*cst + i_*g_;
            float h = o_ * tanh_fast(cst);
            if (t == LL - 1) out[b*DD + rank*32 + j] = h;
            float hop = h * ONX[rank*32 + j];
            #pragma unroll
            for (int o = 16; o > 0; o >>= 1) hop += __shfl_xor_sync(0xffffffffu, hop, o);
            float hn = __shfl_xor_sync(0xffffffffu, h, 1);
            if ((j & 1) == 0) {
                #pragma unroll
                for (int q = 0; q < 4; q++)
                    st_async_f64(r_hb[bufh][q] + (rank*32u + (uint32_t)j)*4u, h, hn, r_hbar[bufh][q]);
            }
            if (j == 0) {
                #pragma unroll
                for (int q = 0; q < 4; q++)
                    st_async_f32(r_hob[q] + rank*4u, hop, r_hbar[bufh][q]);
            }
        }

        // ---- phase5a (all warps, h still in flight): old-mem score dots
        float4 ov = ONX4[lane];
        int r0 = warp*4;
        float4 m[4]; float dd[4];
        #pragma unroll
        for (int li = 0; li < 4; li++) {
            m[li] = MEM4[(r0 + li)*32 + lane];
            dd[li] = m[li].x*ov.x + m[li].y*ov.y + m[li].z*ov.z + m[li].w*ov.w;
        }
        #pragma unroll
        for (int ofs = 16, n = 4; ofs >= 8; ofs >>= 1, n >>= 1) {
            int half = n >> 1;
            bool side = (lane & ofs) != 0;
            #pragma unroll
            for (int i = 0; i < 2; i++) {
                if (i < half) {
                    float send = side ? dd[i] : dd[i + half];
                    float recv = __shfl_xor_sync(0xffffffffu, send, ofs);
                    dd[i] = (side ? dd[i + half] : dd[i]) + recv;
                }
            }
        }
        dd[0] += __shfl_xor_sync(0xffffffffu, dd[0], 4);
        dd[0] += __shfl_xor_sync(0xffffffffu, dd[0], 2);
        dd[0] += __shfl_xor_sync(0xffffffffu, dd[0], 1);

        mbar_wait(hbar[bufh], parh);

        // ---- phase5b: s = (1-z)d + z(h.o); e; mem writeback; PA partials
        float ho = HOB[0] + HOB[1] + HOB[2] + HOB[3];
        if ((lane & 7) == 0) {
            int row = r0 + ((lane >> 3) & 3);
            float z = ZZ[row];
            EE[row] = __expf(dd[0] + z*(ho - dd[0]));
        }
        __syncwarp();
        {
            float4 hv = reinterpret_cast<const float4*>(HB + bufh*128)[lane];
            float4 pacc = make_float4(0.f, 0.f, 0.f, 0.f);
            float u = 0.f;
            #pragma unroll
            for (int li = 0; li < 4; li++) {
                int l = r0 + li;
                float e = EE[l], z = ZZ[l];
                float w = e - e*z;           // e(1-z)
                pacc.x = fmaf(w, m[li].x, pacc.x);
                pacc.y = fmaf(w, m[li].y, pacc.y);
                pacc.z = fmaf(w, m[li].z, pacc.z);
                pacc.w = fmaf(w, m[li].w, pacc.w);
                u += e*z;
                float4 mm = m[li];
                mm.x = fmaf(z, hv.x - mm.x, mm.x);
                mm.y = fmaf(z, hv.y - mm.y, mm.y);
                mm.z = fmaf(z, hv.z - mm.z, mm.z);
                mm.w = fmaf(z, hv.w - mm.w, mm.w);
                MEM4[l*32 + lane] = mm;
            }
            pacc.x = fmaf(u, hv.x, pacc.x);
            pacc.y = fmaf(u, hv.y, pacc.y);
            pacc.z = fmaf(u, hv.z, pacc.z);
            pacc.w = fmaf(u, hv.w, pacc.w);
            PA4[warp*32 + lane] = pacc;
        }
        __syncthreads();                              // F
    }
    CLUSTER_SYNC_();
}

// ---------------------------------------------------------------------------
extern "C" void kernel_launch(void* const* d_in, const int* in_sizes, int n_in,
                              void* d_out, int out_size)
{
    const float* x  = (const float*)d_in[0];
    const float* Wr = (const float*)d_in[1];
    const float* Ur = (const float*)d_in[2];
    const float* br = (const float*)d_in[3];
    const float* Ww = (const float*)d_in[4];
    const float* Uw = (const float*)d_in[5];
    const float* bw = (const float*)d_in[6];
    const float* Wc = (const float*)d_in[7];
    const float* bc = (const float*)d_in[8];
    float* out = (float*)d_out;
    (void)in_sizes; (void)n_in; (void)out_size;

    void *p_xw, *p_pre, *p_oseq, *p_E, *p_cvec;
    cudaGetSymbolAddress(&p_xw,   g_xw);
    cudaGetSymbolAddress(&p_pre,  g_pre);
    cudaGetSymbolAddress(&p_oseq, g_oseq);
    cudaGetSymbolAddress(&p_E,    g_E);
    cudaGetSymbolAddress(&p_cvec, g_cvec);

    cudaFuncSetAttribute(reader_kernel,
                         cudaFuncAttributeMaxDynamicSharedMemorySize,
                         R_TOT * (int)sizeof(float));
    cudaFuncSetAttribute(writer_kernel,
                         cudaFuncAttributeMaxDynamicSharedMemorySize,
                         W_TOT * (int)sizeof(float));

    dim3 gdim(GG/64, (BB*LL)/64);

    gemm_k128_n512<<<gdim, 256>>>(x, Wr, br, (float*)p_xw);
    prep_EF<<<DD, 512>>>(Wc, Ww, bc, bw, Uw, Ur);
    reader_kernel<<<4*BB, 512, R_TOT * (int)sizeof(float)>>>();
    gemm_k128_n512<<<gdim, 256>>>((const float*)p_oseq, (const float*)p_E,
                                  (const float*)p_cvec, (float*)p_pre);
    nop_kernel<<<1, 32>>>();
    writer_kernel<<<4*BB, 512, W_TOT * (int)sizeof(float)>>>(x, out);
}

// round 13
// speedup vs baseline: 1.7374x; 1.0855x over previous
#include <cuda_runtime.h>
#include <cuda_fp16.h>
#include <math.h>
#include <stdint.h>

#define BB 32
#define LL 256
#define DD 128
#define GG 512

__device__ float g_xw  [BB*LL*GG];   // x @ Wr + br
// fp16, transposed, rank-sliced, gate-permuted weights:
// c = g*32 + jj  <->  global col = g*128 + r*32 + jj
__device__ __align__(16) __half g_W2Th[4*128*256];  // k: 0..127 Uw, 128..255 F
__device__ __align__(16) __half g_ETh [4*128*128];  // E = Wc_top@Ww
__device__ __align__(16) __half g_URh [4*128*128];  // Ur
__device__ float g_cvec[GG];                        // bc@Ww + bw

__device__ __forceinline__ float hsig(float x) {
    return fminf(fmaxf(0.2f*x + 0.5f, 0.0f), 1.0f);
}
__device__ __forceinline__ float tanh_fast(float x) {
    float e = __expf(fminf(2.0f*x, 80.0f));
    return 1.0f - __fdividef(2.0f, e + 1.0f);
}
__device__ __forceinline__ uint32_t smem_u32(const void* p) {
    uint32_t a;
    asm("{ .reg .u64 t; cvta.to.shared.u64 t, %1; cvt.u32.u64 %0, t; }" : "=r"(a) : "l"(p));
    return a;
}
__device__ __forceinline__ uint32_t ctarank() {
    uint32_t r; asm("mov.u32 %0, %%cluster_ctarank;" : "=r"(r)); return r;
}
__device__ __forceinline__ uint32_t mapa_u32(uint32_t a, uint32_t rk) {
    uint32_t o; asm("mapa.shared::cluster.u32 %0, %1, %2;" : "=r"(o) : "r"(a), "r"(rk)); return o;
}
__device__ __forceinline__ void mbar_init(uint32_t a, uint32_t cnt) {
    asm volatile("mbarrier.init.shared.b64 [%0], %1;" :: "r"(a), "r"(cnt) : "memory");
}
__device__ __forceinline__ void mbar_arrive_expect(uint32_t a, uint32_t tx) {
    asm volatile("mbarrier.arrive.expect_tx.shared.b64 _, [%0], %1;" :: "r"(a), "r"(tx) : "memory");
}
__device__ __forceinline__ void mbar_wait(uint32_t a, uint32_t parity) {
    uint32_t done;
    asm volatile("{\n\t.reg .pred p;\n\t"
        "mbarrier.try_wait.parity.acquire.cta.shared::cta.b64 p, [%1], %2;\n\t"
        "selp.b32 %0, 1, 0, p;\n\t}" : "=r"(done) : "r"(a), "r"(parity) : "memory");
    if (!done) {
        asm volatile("{\n\t.reg .pred P1;\n\tWL_%=:\n\t"
            "mbarrier.try_wait.parity.acquire.cta.shared::cta.b64 P1, [%0], %1, 0x989680;\n\t"
            "@P1 bra.uni WD_%=;\n\tbra.uni WL_%=;\n\tWD_%=:\n\t}"
            :: "r"(a), "r"(parity) : "memory");
    }
}
__device__ __forceinline__ void st_async_f32(uint32_t ra, float v, uint32_t rmb) {
    asm volatile("st.async.shared::cluster.mbarrier::complete_tx::bytes.b32 [%0], %1, [%2];"
                 :: "r"(ra), "r"(__float_as_uint(v)), "r"(rmb) : "memory");
}
__device__ __forceinline__ void st_async_f64(uint32_t ra, float a, float b, uint32_t rmb) {
    unsigned long long v = ((unsigned long long)__float_as_uint(b) << 32) | __float_as_uint(a);
    asm volatile("st.async.shared::cluster.mbarrier::complete_tx::bytes.b64 [%0], %1, [%2];"
                 :: "r"(ra), "l"(v), "r"(rmb) : "memory");
}
#define CLUSTER_SYNC_() do { \
    asm volatile("barrier.cluster.arrive.aligned;" ::: "memory"); \
    asm volatile("barrier.cluster.wait.aligned;" ::: "memory"); } while (0)

__device__ __forceinline__ void red8_store(float* p, int lane, float* dst) {
    #pragma unroll
    for (int ofs = 16, n = 8; ofs >= 4; ofs >>= 1, n >>= 1) {
        int half = n >> 1;
        bool side = (lane & ofs) != 0;
        #pragma unroll
        for (int i = 0; i < 4; i++) {
            if (i < half) {
                float send = side ? p[i] : p[i + half];
                float recv = __shfl_xor_sync(0xffffffffu, send, ofs);
                p[i] = (side ? p[i + half] : p[i]) + recv;
            }
        }
    }
    p[0] += __shfl_xor_sync(0xffffffffu, p[0], 2);
    p[0] += __shfl_xor_sync(0xffffffffu, p[0], 1);
    if ((lane & 3) == 0) dst[(lane >> 2) & 7] = p[0];
}

__device__ __forceinline__ float dot4_h(uint2 w, float4 hv) {
    float2 a = __half22float2(*reinterpret_cast<__half2*>(&w.x));
    float2 b = __half22float2(*reinterpret_cast<__half2*>(&w.y));
    return hv.x*a.x + hv.y*a.y + hv.z*b.x + hv.w*b.y;
}

// ---------------- GEMM: C[M,512] = A[M,128] @ W[128,512] + bias ------------
__global__ void __launch_bounds__(256) gemm_k128_n512(
        const float* __restrict__ A, const float* __restrict__ W,
        const float* __restrict__ bias, float* __restrict__ C)
{
    __shared__ __align__(16) float As[64][68];
    __shared__ __align__(16) float Ws[64][64];
    int tid = threadIdx.x, tx = tid & 15, ty = tid >> 4;
    int n0 = blockIdx.x * 64;
    long r0 = (long)blockIdx.y * 64;
    float acc[4][4] = {};
    for (int kc = 0; kc < 128; kc += 64) {
        #pragma unroll
        for (int i = 0; i < 4; i++) {
            int f = tid + i*256, row = f >> 4, c4 = (f & 15) * 4;
            *reinterpret_cast<float4*>(&As[row][c4]) =
                *reinterpret_cast<const float4*>(A + (r0 + row)*128 + kc + c4);
            *reinterpret_cast<float4*>(&Ws[row][c4]) =
                *reinterpret_cast<const float4*>(W + (long)(kc + row)*GG + n0 + c4);
        }
        __syncthreads();
        #pragma unroll
        for (int k = 0; k < 64; k++) {
            float4 wv = *reinterpret_cast<const float4*>(&Ws[k][tx*4]);
            #pragma unroll
            for (int i = 0; i < 4; i++) {
                float a = As[ty*4 + i][k];
                acc[i][0] += a*wv.x; acc[i][1] += a*wv.y;
                acc[i][2] += a*wv.z; acc[i][3] += a*wv.w;
            }
        }
        __syncthreads();
    }
    int col = n0 + tx*4;
    float4 bv = *reinterpret_cast<const float4*>(bias + col);
    #pragma unroll
    for (int i = 0; i < 4; i++) {
        float4 o;
        o.x = acc[i][0] + bv.x; o.y = acc[i][1] + bv.y;
        o.z = acc[i][2] + bv.z; o.w = acc[i][3] + bv.w;
        *reinterpret_cast<float4*>(C + (r0 + ty*4 + i)*GG + col) = o;
    }
}

// ---------------- prep: fp16 transposed W2T/ET/URt, cvec -------------------
__global__ void __launch_bounds__(512) prep_EF(
        const float* __restrict__ Wc, const float* __restrict__ Ww,
        const float* __restrict__ bc, const float* __restrict__ bw,
        const float* __restrict__ Uw, const float* __restrict__ Ur)
{
    __shared__ float st[DD], sb[DD], sc[DD];
    int d = blockIdx.x, j = threadIdx.x;
    if (j < DD) { st[j] = Wc[d*DD + j]; sb[j] = Wc[(DD + d)*DD + j]; sc[j] = bc[j]; }
    __syncthreads();
    float e = 0.f, f = 0.f, cv = 0.f;
    #pragma unroll 8
    for (int c = 0; c < DD; c++) {
        float w = Ww[c*GG + j];
        e += st[c]*w; f += sb[c]*w; cv += sc[c]*w;
    }
    int g = j >> 7, r = (j >> 5) & 3, jj = j & 31;
    int c = g*32 + jj;
    g_W2Th[(r*128 + c)*256 + d]       = __float2half(Uw[d*GG + j]);
    g_W2Th[(r*128 + c)*256 + 128 + d] = __float2half(f);
    g_ETh [(r*128 + c)*128 + d]       = __float2half(e);
    g_URh [(r*128 + c)*128 + d]       = __float2half(Ur[d*GG + j]);
    if (d == 0) g_cvec[j] = cv + bw[j];
}

// ---------------- fused kernel: reader (1 step ahead) + writer -------------
// smem float offsets
#define M_W2   0        // UwF half [128][256]   (16384)
#define M_EU   16384    // E half [128][128]     (8192)
#define M_UR   24576    // Ur half [128][128]    (8192)
#define M_MEM  32768    // [64][128]             (8192)
#define M_PA   40960    // [16][128]             (2048)
#define M_MRTB 43008    // [4][128]              (512)
#define M_CVEC 43520    // [128]
#define M_ZS   43648    // [128]
#define M_ZSR  43776    // [128]
#define M_XWR  43904    // [2][128]
#define M_HRB  44160    // [2][128] o boxes
#define M_HWB  44416    // [2][128] h boxes
#define M_MRT  44672    // [128]
#define M_ZZ   44800    // [64]
#define M_EE   44864    // [64]
#define M_ONXL 44928    // [32]
#define M_SB   44960    // [4]
#define M_HOB  44964    // [4]
#define M_MB   44968    // 5 bars (10 floats); 44968*4 % 8 == 0
#define M_TOT  44978

__global__ void __launch_bounds__(512) __cluster_dims__(4, 1, 1)
fused_kernel(const float* __restrict__ x, float* __restrict__ out)
{
    extern __shared__ __align__(16) float sm[];
    float* MEM  = sm + M_MEM;
    float* PA   = sm + M_PA;
    float* MRTB = sm + M_MRTB;
    float* CVEC = sm + M_CVEC;
    float* ZS   = sm + M_ZS;
    float* ZSR  = sm + M_ZSR;
    float* XWR  = sm + M_XWR;
    float* HRB  = sm + M_HRB;
    float* HWB  = sm + M_HWB;
    float* MRT  = sm + M_MRT;
    float* ZZ   = sm + M_ZZ;
    float* EE   = sm + M_EE;
    float* ONXL = sm + M_ONXL;
    float* SB   = sm + M_SB;
    float* HOB  = sm + M_HOB;
    const uint2* W2u = reinterpret_cast<const uint2*>(sm + M_W2);  // 64 uint2/col
    const uint2* EUu = reinterpret_cast<const uint2*>(sm + M_EU);  // 32 uint2/col
    const uint2* URu = reinterpret_cast<const uint2*>(sm + M_UR);  // 32 uint2/col

    int tid = threadIdx.x, lane = tid & 31, warp = tid >> 5;
    uint32_t rank = ctarank();
    int b = blockIdx.x >> 2;

    uint32_t mrt_bar = smem_u32(sm + M_MB);
    uint32_t hwbar[2] = { smem_u32(sm + M_MB + 2), smem_u32(sm + M_MB + 4) };
    uint32_t hrbar[2] = { smem_u32(sm + M_MB + 6), smem_u32(sm + M_MB + 8) };
    if (tid == 0) {
        mbar_init(mrt_bar, 1);
        mbar_init(hwbar[0], 1); mbar_init(hwbar[1], 1);
        mbar_init(hrbar[0], 1); mbar_init(hrbar[1], 1);
    }

    const float* xwb = g_xw + (long)b*LL*GG;

    // weight slices -> smem (fp16)
    {
        uint4* dst = reinterpret_cast<uint4*>(sm + M_W2);
        const uint4* src = reinterpret_cast<const uint4*>(g_W2Th) + (long)rank*4096;
        for (int i = tid; i < 4096; i += 512) dst[i] = src[i];
        uint4* dstE = reinterpret_cast<uint4*>(sm + M_EU);
        const uint4* srcE = reinterpret_cast<const uint4*>(g_ETh) + (long)rank*2048;
        for (int i = tid; i < 2048; i += 512) dstE[i] = srcE[i];
        uint4* dstU = reinterpret_cast<uint4*>(sm + M_UR);
        const uint4* srcU = reinterpret_cast<const uint4*>(g_URh) + (long)rank*2048;
        for (int i = tid; i < 2048; i += 512) dstU[i] = srcU[i];
    }
    // mem slice
    {
        const float* xb = x + ((long)b*LL + rank*64)*DD;
        for (int i = tid; i < 64*DD; i += 512) MEM[i] = xb[i];
    }
    if (tid < 256) HWB[tid] = 0.f;
    if (tid < 128) {
        // reader step 0: h=0 so z = xw(0) only; compute o_0 and c_r(0)
        float zi = xwb[tid], zg = xwb[256 + tid], zo = xwb[384 + tid];
        float c0 = hsig(zi) * tanh_fast(zg);
        float o0 = hsig(zo) * tanh_fast(c0);
        HRB[128 + tid] = o0;   // prev buf for t=0
        HRB[tid] = 0.f;
        ZSR[tid] = c0;         // stash c_r(0)
        // xw for reader step 1 (permuted cols)
        XWR[tid] = xwb[GG + (tid >> 5)*128 + rank*32 + (tid & 31)];
        CVEC[tid] = g_cvec[(tid >> 5)*128 + rank*32 + (tid & 31)];
    }
    float cst_w = 0.f, cst_r = 0.f;
    __syncthreads();
    if (warp == 2) cst_r = ZSR[rank*32 + lane];
    CLUSTER_SYNC_();

    uint32_t r_mrtb[4], r_sb[4], r_mbar[4];
    uint32_t r_hwb[2][4], r_hwbar[2][4], r_hob[4];
    uint32_t r_hrb[2][4], r_hrbar[2][4];
    #pragma unroll
    for (int q = 0; q < 4; q++) {
        uint32_t pr = (rank + 1 + q) & 3;   // q=3 -> self
        r_mrtb[q] = mapa_u32(smem_u32(MRTB), pr);
        r_sb[q]   = mapa_u32(smem_u32(SB), pr);
        r_mbar[q] = mapa_u32(mrt_bar, pr);
        r_hwbar[0][q] = mapa_u32(hwbar[0], pr);
        r_hwbar[1][q] = mapa_u32(hwbar[1], pr);
        r_hwb[0][q]   = mapa_u32(smem_u32(HWB), pr);
        r_hwb[1][q]   = mapa_u32(smem_u32(HWB + 128), pr);
        r_hob[q]      = mapa_u32(smem_u32(HOB), pr);
        r_hrbar[0][q] = mapa_u32(hrbar[0], pr);
        r_hrbar[1][q] = mapa_u32(hrbar[1], pr);
        r_hrb[0][q]   = mapa_u32(smem_u32(HRB), pr);
        r_hrb[1][q]   = mapa_u32(smem_u32(HRB + 128), pr);
    }

    float4* MEM4 = reinterpret_cast<float4*>(MEM);
    float4* PA4  = reinterpret_cast<float4*>(PA);
    const float2* PA2 = reinterpret_cast<const float2*>(PA);
    const float4* MRT4 = reinterpret_cast<const float4*>(MRT);

    // ---- initial scores: s_0 = o_0 . mem -> EE, PA ------------------------
    {
        float4 ov = reinterpret_cast<const float4*>(HRB + 128)[lane];
        int r0 = warp*4;
        float4 m[4]; float pr_[4];
        #pragma unroll
        for (int li = 0; li < 4; li++) {
            m[li] = MEM4[(r0 + li)*32 + lane];
            pr_[li] = m[li].x*ov.x + m[li].y*ov.y + m[li].z*ov.z + m[li].w*ov.w;
        }
        #pragma unroll
        for (int ofs = 16, n = 4; ofs >= 8; ofs >>= 1, n >>= 1) {
            int half = n >> 1;
            bool side = (lane & ofs) != 0;
            #pragma unroll
            for (int i = 0; i < 2; i++) {
                if (i < half) {
                    float send = side ? pr_[i] : pr_[i + half];
                    float recv = __shfl_xor_sync(0xffffffffu, send, ofs);
                    pr_[i] = (side ? pr_[i + half] : pr_[i]) + recv;
                }
            }
        }
        pr_[0] += __shfl_xor_sync(0xffffffffu, pr_[0], 4);
        pr_[0] += __shfl_xor_sync(0xffffffffu, pr_[0], 2);
        pr_[0] += __shfl_xor_sync(0xffffffffu, pr_[0], 1);
        if ((lane & 7) == 0) EE[r0 + ((lane >> 3) & 3)] = __expf(pr_[0]);
        __syncwarp();
        float4 pacc = make_float4(0.f, 0.f, 0.f, 0.f);
        #pragma unroll
        for (int li = 0; li < 4; li++) {
            float e = EE[r0 + li];
            pacc.x = fmaf(e, m[li].x, pacc.x);
            pacc.y = fmaf(e, m[li].y, pacc.y);
            pacc.z = fmaf(e, m[li].z, pacc.z);
            pacc.w = fmaf(e, m[li].w, pacc.w);
        }
        PA4[warp*32 + lane] = pacc;
    }
    __syncthreads();

    for (int t = 0; t < LL; t++) {
        int buf = t & 1, prev = buf ^ 1;
        int parh = (t >> 1) & 1, parm = t & 1;
        if (tid == 0) {
            mbar_arrive_expect(mrt_bar, 2064);       // 4 x (512 + 4)
            mbar_arrive_expect(hwbar[buf], 528);     // 4 x (128 + 4)
            mbar_arrive_expect(hrbar[buf], 512);     // 4 x 128
        }
        // ---- phase1: sends + prefetch, then fused GEMVs (reader + Uw + E)
        if (tid < 64) {
            float2 p = make_float2(0.f, 0.f);
            #pragma unroll
            for (int w = 0; w < 16; w++) {
                float2 v = PA2[w*64 + tid];
                p.x += v.x; p.y += v.y;
            }
            #pragma unroll
            for (int q = 0; q < 4; q++)
                st_async_f64(r_mrtb[q] + (rank*128u + 2u*(uint32_t)tid)*4u, p.x, p.y, r_mbar[q]);
        } else if (tid >= 96 && tid < 128) {
            float v = EE[lane] + EE[32 + lane];
            #pragma unroll
            for (int o = 16; o > 0; o >>= 1) v += __shfl_xor_sync(0xffffffffu, v, o);
            if (lane == 0) {
                #pragma unroll
                for (int q = 0; q < 4; q++)
                    st_async_f32(r_sb[q] + rank*4u, v, r_mbar[q]);
            }
        } else if (tid >= 128 && tid < 192) {
            int i = (tid - 128)*2;
            int tn2 = (t + 2 < LL) ? t + 2 : LL - 1;
            XWR[prev*128 + i]     = xwb[tn2*GG + (i >> 5)*128 + rank*32 + (i & 31)];
            XWR[prev*128 + i + 1] = xwb[tn2*GG + ((i+1) >> 5)*128 + rank*32 + ((i+1) & 31)];
        }
        float accR[8], acc[8];
        {
            float4 ovt = reinterpret_cast<const float4*>(HRB + prev*128)[lane]; // o_t
            float4 hwv = reinterpret_cast<const float4*>(HWB + prev*128)[lane]; // h_w(t)
            #pragma unroll
            for (int i = 0; i < 8; i++) {
                int c = warp*8 + i;
                accR[i] = dot4_h(URu[c*32 + lane], ovt);
                acc[i]  = dot4_h(W2u[c*64 + lane], hwv) + dot4_h(EUu[c*32 + lane], ovt);
            }
            red8_store(accR, lane, ZSR + warp*8);
        }
        __syncthreads();                              // S1

        // ---- phase0b (warp2): reader gates -> o_{t+1}, send hr
        if (warp == 2) {
            int j = lane;
            float i_ = hsig (ZSR[j]      + XWR[buf*128 + j]);
            float f_ = hsig (ZSR[32 + j] + XWR[buf*128 + 32 + j]);
            float g_ = tanh_fast(ZSR[64 + j] + XWR[buf*128 + 64 + j]);
            float o_ = hsig (ZSR[96 + j] + XWR[buf*128 + 96 + j]);
            cst_r = f_*cst_r + i_*g_;
            float hr = o_ * tanh_fast(cst_r);
            ONXL[j] = hr;
            float hn = __shfl_xor_sync(0xffffffffu, hr, 1);
            if ((j & 1) == 0) {
                #pragma unroll
                for (int q = 0; q < 4; q++)
                    st_async_f64(r_hrb[buf][q] + (rank*32u + (uint32_t)j)*4u, hr, hn, r_hrbar[buf][q]);
            }
        }
        // ---- phase2 (warps 4-9): wait mrt, combine
        if (warp >= 4 && warp < 8) {
            mbar_wait(mrt_bar, parm);
            int d = tid - 128;
            float inv = 1.0f / (SB[0] + SB[1] + SB[2] + SB[3]);
            MRT[d] = (MRTB[d] + MRTB[128 + d] + MRTB[256 + d] + MRTB[384 + d]) * inv;
        } else if (warp >= 8 && warp < 10) {
            mbar_wait(mrt_bar, parm);
            int d = tid - 256;
            float inv = 1.0f / (SB[0] + SB[1] + SB[2] + SB[3]);
            ZZ[d] = EE[d] * inv;
        }
        __syncthreads();                              // S2

        // ---- phase3: F-half GEMV + reduce -> ZS
        {
            float4 mv = MRT4[lane];
            #pragma unroll
            for (int i = 0; i < 8; i++)
                acc[i] += dot4_h(W2u[(warp*8 + i)*64 + 32 + lane], mv);
            red8_store(acc, lane, ZS + warp*8);
        }
        __syncthreads();                              // S3

        // ---- phase4 (warp0): writer gates + h/ho send
        if (warp == 0) {
            int j = lane;
            float i_ = hsig (ZS[j]      + CVEC[j]);
            float f_ = hsig (ZS[32 + j] + CVEC[32 + j]);
            float g_ = tanh_fast(ZS[64 + j] + CVEC[64 + j]);
            float o_ = hsig (ZS[96 + j] + CVEC[96 + j]);
            cst_w = f_*cst_w + i_*g_;
            float h = o_ * tanh_fast(cst_w);
            if (t == LL - 1) out[b*DD + rank*32 + j] = h;
            float hop = h * ONXL[j];
            #pragma unroll
            for (int o = 16; o > 0; o >>= 1) hop += __shfl_xor_sync(0xffffffffu, hop, o);
            float hn = __shfl_xor_sync(0xffffffffu, h, 1);
            if ((j & 1) == 0) {
                #pragma unroll
                for (int q = 0; q < 4; q++)
                    st_async_f64(r_hwb[buf][q] + (rank*32u + (uint32_t)j)*4u, h, hn, r_hwbar[buf][q]);
            }
            if (j == 0) {
                #pragma unroll
                for (int q = 0; q < 4; q++)
                    st_async_f32(r_hob[q] + rank*4u, hop, r_hwbar[buf][q]);
            }
        }

        // ---- phase5: wait o_{t+1}; old-mem dots; wait h; finish
        mbar_wait(hrbar[buf], parh);
        float4 ov = reinterpret_cast<const float4*>(HRB + buf*128)[lane];  // o_{t+1}
        int r0 = warp*4;
        float4 m[4]; float dd[4];
        #pragma unroll
        for (int li = 0; li < 4; li++) {
            m[li] = MEM4[(r0 + li)*32 + lane];
            dd[li] = m[li].x*ov.x + m[li].y*ov.y + m[li].z*ov.z + m[li].w*ov.w;
        }
        #pragma unroll
        for (int ofs = 16, n = 4; ofs >= 8; ofs >>= 1, n >>= 1) {
            int half = n >> 1;
            bool side = (lane & ofs) != 0;
            #pragma unroll
            for (int i = 0; i < 2; i++) {
                if (i < half) {
                    float send = side ? dd[i] : dd[i + half];
                    float recv = __shfl_xor_sync(0xffffffffu, send, ofs);
                    dd[i] = (side ? dd[i + half] : dd[i]) + recv;
                }
            }
        }
        dd[0] += __shfl_xor_sync(0xffffffffu, dd[0], 4);
        dd[0] += __shfl_xor_sync(0xffffffffu, dd[0], 2);
        dd[0] += __shfl_xor_sync(0xffffffffu, dd[0], 1);

        mbar_wait(hwbar[buf], parh);

        float ho = HOB[0] + HOB[1] + HOB[2] + HOB[3];
        if ((lane & 7) == 0) {
            int row = r0 + ((lane >> 3) & 3);
            float z = ZZ[row];
            EE[row] = __expf(dd[0] + z*(ho - dd[0]));
        }
        __syncwarp();
        {
            float4 hv = reinterpret_cast<const float4*>(HWB + buf*128)[lane];
            float4 pacc = make_float4(0.f, 0.f, 0.f, 0.f);
            float u = 0.f;
            #pragma unroll
            for (int li = 0; li < 4; li++) {
                int l = r0 + li;
                float e = EE[l], z = ZZ[l];
                float w = e - e*z;
                pacc.x = fmaf(w, m[li].x, pacc.x);
                pacc.y = fmaf(w, m[li].y, pacc.y);
                pacc.z = fmaf(w, m[li].z, pacc.z);
                pacc.w = fmaf(w, m[li].w, pacc.w);
                u += e*z;
                float4 mm = m[li];
                mm.x = fmaf(z, hv.x - mm.x, mm.x);
                mm.y = fmaf(z, hv.y - mm.y, mm.y);
                mm.z = fmaf(z, hv.z - mm.z, mm.z);
                mm.w = fmaf(z, hv.w - mm.w, mm.w);
                MEM4[l*32 + lane] = mm;
            }
            pacc.x = fmaf(u, hv.x, pacc.x);
            pacc.y = fmaf(u, hv.y, pacc.y);
            pacc.z = fmaf(u, hv.z, pacc.z);
            pacc.w = fmaf(u, hv.w, pacc.w);
            PA4[warp*32 + lane] = pacc;
        }
        __syncthreads();                              // SF
    }
    CLUSTER_SYNC_();
}

// ---------------------------------------------------------------------------
extern "C" void kernel_launch(void* const* d_in, const int* in_sizes, int n_in,
                              void* d_out, int out_size)
{
    const float* x  = (const float*)d_in[0];
    const float* Wr = (const float*)d_in[1];
    const float* Ur = (const float*)d_in[2];
    const float* br = (const float*)d_in[3];
    const float* Ww = (const float*)d_in[4];
    const float* Uw = (const float*)d_in[5];
    const float* bw = (const float*)d_in[6];
    const float* Wc = (const float*)d_in[7];
    const float* bc = (const float*)d_in[8];
    float* out = (float*)d_out;
    (void)in_sizes; (void)n_in; (void)out_size;

    void* p_xw;
    cudaGetSymbolAddress(&p_xw, g_xw);

    cudaFuncSetAttribute(fused_kernel,
                         cudaFuncAttributeMaxDynamicSharedMemorySize,
                         M_TOT * (int)sizeof(float));

    dim3 gdim(GG/64, (BB*LL)/64);

    // 0) xw = x @ Wr + br
    gemm_k128_n512<<<gdim, 256>>>(x, Wr, br, (float*)p_xw);
    // 1) fold weights: W2T (Uw,F), ET, URt, cvec
    prep_EF<<<DD, 512>>>(Wc, Ww, bc, bw, Uw, Ur);
    // 2) fused reader+writer scan (reader runs one step ahead in-cluster)
    fused_kernel<<<4*BB, 512, M_TOT * (int)sizeof(float)>>>(x, out);
}

// round 15
// speedup vs baseline: 1.8494x; 1.0644x over previous
#include <cuda_runtime.h>
#include <cuda_fp16.h>
#include <math.h>
#include <stdint.h>

#define BB 32
#define LL 256
#define DD 128
#define GG 512

__device__ float g_xw  [BB*LL*GG];   // x @ Wr + br
// fp16, transposed, rank-sliced, gate-permuted weights:
// c = g*32 + jj  <->  global col = g*128 + r*32 + jj
__device__ __align__(16) __half g_W2Th[4*128*256];  // k: 0..127 Uw, 128..255 F
__device__ __align__(16) __half g_ETh [4*128*128];  // E = Wc_top@Ww
__device__ __align__(16) __half g_URh [4*128*128];  // Ur
__device__ float g_cvec[GG];                        // bc@Ww + bw

__device__ __forceinline__ float hsig(float x) {
    return fminf(fmaxf(0.2f*x + 0.5f, 0.0f), 1.0f);
}
__device__ __forceinline__ float tanh_fast(float x) {
    float e = __expf(fminf(2.0f*x, 80.0f));
    return 1.0f - __fdividef(2.0f, e + 1.0f);
}
__device__ __forceinline__ uint32_t smem_u32(const void* p) {
    uint32_t a;
    asm("{ .reg .u64 t; cvta.to.shared.u64 t, %1; cvt.u32.u64 %0, t; }" : "=r"(a) : "l"(p));
    return a;
}
__device__ __forceinline__ uint32_t ctarank() {
    uint32_t r; asm("mov.u32 %0, %%cluster_ctarank;" : "=r"(r)); return r;
}
__device__ __forceinline__ uint32_t mapa_u32(uint32_t a, uint32_t rk) {
    uint32_t o; asm("mapa.shared::cluster.u32 %0, %1, %2;" : "=r"(o) : "r"(a), "r"(rk)); return o;
}
__device__ __forceinline__ void mbar_init(uint32_t a, uint32_t cnt) {
    asm volatile("mbarrier.init.shared.b64 [%0], %1;" :: "r"(a), "r"(cnt) : "memory");
}
__device__ __forceinline__ void mbar_arrive_expect(uint32_t a, uint32_t tx) {
    asm volatile("mbarrier.arrive.expect_tx.shared.b64 _, [%0], %1;" :: "r"(a), "r"(tx) : "memory");
}
__device__ __forceinline__ void mbar_wait(uint32_t a, uint32_t parity) {
    uint32_t done;
    asm volatile("{\n\t.reg .pred p;\n\t"
        "mbarrier.try_wait.parity.acquire.cta.shared::cta.b64 p, [%1], %2;\n\t"
        "selp.b32 %0, 1, 0, p;\n\t}" : "=r"(done) : "r"(a), "r"(parity) : "memory");
    if (!done) {
        asm volatile("{\n\t.reg .pred P1;\n\tWL_%=:\n\t"
            "mbarrier.try_wait.parity.acquire.cta.shared::cta.b64 P1, [%0], %1, 0x989680;\n\t"
            "@P1 bra.uni WD_%=;\n\tbra.uni WL_%=;\n\tWD_%=:\n\t}"
            :: "r"(a), "r"(parity) : "memory");
    }
}
__device__ __forceinline__ void st_async_f32(uint32_t ra, float v, uint32_t rmb) {
    asm volatile("st.async.shared::cluster.mbarrier::complete_tx::bytes.b32 [%0], %1, [%2];"
                 :: "r"(ra), "r"(__float_as_uint(v)), "r"(rmb) : "memory");
}
__device__ __forceinline__ void st_async_f64(uint32_t ra, float a, float b, uint32_t rmb) {
    unsigned long long v = ((unsigned long long)__float_as_uint(b) << 32) | __float_as_uint(a);
    asm volatile("st.async.shared::cluster.mbarrier::complete_tx::bytes.b64 [%0], %1, [%2];"
                 :: "r"(ra), "l"(v), "r"(rmb) : "memory");
}
#define CLUSTER_SYNC_() do { \
    asm volatile("barrier.cluster.arrive.aligned;" ::: "memory"); \
    asm volatile("barrier.cluster.wait.aligned;" ::: "memory"); } while (0)

__device__ __forceinline__ void red8_store(float* p, int lane, float* dst) {
    #pragma unroll
    for (int ofs = 16, n = 8; ofs >= 4; ofs >>= 1, n >>= 1) {
        int half = n >> 1;
        bool side = (lane & ofs) != 0;
        #pragma unroll
        for (int i = 0; i < 4; i++) {
            if (i < half) {
                float send = side ? p[i] : p[i + half];
                float recv = __shfl_xor_sync(0xffffffffu, send, ofs);
                p[i] = (side ? p[i + half] : p[i]) + recv;
            }
        }
    }
    p[0] += __shfl_xor_sync(0xffffffffu, p[0], 2);
    p[0] += __shfl_xor_sync(0xffffffffu, p[0], 1);
    if ((lane & 3) == 0) dst[(lane >> 2) & 7] = p[0];
}

__device__ __forceinline__ float dot4_h(uint2 w, float4 hv) {
    float2 a = __half22float2(*reinterpret_cast<__half2*>(&w.x));
    float2 b = __half22float2(*reinterpret_cast<__half2*>(&w.y));
    return hv.x*a.x + hv.y*a.y + hv.z*b.x + hv.w*b.y;
}

// ---------------- GEMM: C[M,512] = A[M,128] @ W[128,512] + bias ------------
__global__ void __launch_bounds__(256) gemm_k128_n512(
        const float* __restrict__ A, const float* __restrict__ W,
        const float* __restrict__ bias, float* __restrict__ C)
{
    __shared__ __align__(16) float As[64][68];
    __shared__ __align__(16) float Ws[64][64];
    int tid = threadIdx.x, tx = tid & 15, ty = tid >> 4;
    int n0 = blockIdx.x * 64;
    long r0 = (long)blockIdx.y * 64;
    float acc[4][4] = {};
    for (int kc = 0; kc < 128; kc += 64) {
        #pragma unroll
        for (int i = 0; i < 4; i++) {
            int f = tid + i*256, row = f >> 4, c4 = (f & 15) * 4;
            *reinterpret_cast<float4*>(&As[row][c4]) =
                *reinterpret_cast<const float4*>(A + (r0 + row)*128 + kc + c4);
            *reinterpret_cast<float4*>(&Ws[row][c4]) =
                *reinterpret_cast<const float4*>(W + (long)(kc + row)*GG + n0 + c4);
        }
        __syncthreads();
        #pragma unroll
        for (int k = 0; k < 64; k++) {
            float4 wv = *reinterpret_cast<const float4*>(&Ws[k][tx*4]);
            #pragma unroll
            for (int i = 0; i < 4; i++) {
                float a = As[ty*4 + i][k];
                acc[i][0] += a*wv.x; acc[i][1] += a*wv.y;
                acc[i][2] += a*wv.z; acc[i][3] += a*wv.w;
            }
        }
        __syncthreads();
    }
    int col = n0 + tx*4;
    float4 bv = *reinterpret_cast<const float4*>(bias + col);
    #pragma unroll
    for (int i = 0; i < 4; i++) {
        float4 o;
        o.x = acc[i][0] + bv.x; o.y = acc[i][1] + bv.y;
        o.z = acc[i][2] + bv.z; o.w = acc[i][3] + bv.w;
        *reinterpret_cast<float4*>(C + (r0 + ty*4 + i)*GG + col) = o;
    }
}

// ---------------- prep: fp16 transposed W2T/ET/URt, cvec -------------------
__global__ void __launch_bounds__(512) prep_EF(
        const float* __restrict__ Wc, const float* __restrict__ Ww,
        const float* __restrict__ bc, const float* __restrict__ bw,
        const float* __restrict__ Uw, const float* __restrict__ Ur)
{
    __shared__ float st[DD], sb[DD], sc[DD];
    int d = blockIdx.x, j = threadIdx.x;
    if (j < DD) { st[j] = Wc[d*DD + j]; sb[j] = Wc[(DD + d)*DD + j]; sc[j] = bc[j]; }
    __syncthreads();
    float e = 0.f, f = 0.f, cv = 0.f;
    #pragma unroll 8
    for (int c = 0; c < DD; c++) {
        float w = Ww[c*GG + j];
        e += st[c]*w; f += sb[c]*w; cv += sc[c]*w;
    }
    int g = j >> 7, r = (j >> 5) & 3, jj = j & 31;
    int c = g*32 + jj;
    g_W2Th[(r*128 + c)*256 + d]       = __float2half(Uw[d*GG + j]);
    g_W2Th[(r*128 + c)*256 + 128 + d] = __float2half(f);
    g_ETh [(r*128 + c)*128 + d]       = __float2half(e);
    g_URh [(r*128 + c)*128 + d]       = __float2half(Ur[d*GG + j]);
    if (d == 0) g_cvec[j] = cv + bw[j];
}

// ---------------- fused kernel: reader 1 ahead + writer, reg-resident mem --
// smem float offsets
#define M_W2   0        // UwF half [128][256]   (16384)
#define M_EU   16384    // E half [128][128]     (8192)
#define M_UR   24576    // Ur half [128][128]    (8192)
#define M_PA   32768    // [16][128]             (2048)
#define M_MRTB 34816    // [4][128]              (512)
#define M_CVEC 35328    // [128]
#define M_ZS   35456    // [128]
#define M_ZSR  35584    // [128]
#define M_XWR  35712    // [2][128]
#define M_HRB  35968    // [2][128] o boxes
#define M_HWB  36224    // [2][128] h boxes
#define M_EE   36480    // [64]
#define M_ONXL 36544    // [32]
#define M_SB   36576    // [4]
#define M_HOB  36580    // [4]
#define M_MB   36584    // 5 bars (10 floats); 36584*4 % 8 == 0
#define M_TOT  36594

__global__ void __launch_bounds__(512, 1) __cluster_dims__(4, 1, 1)
fused_kernel(const float* __restrict__ x, float* __restrict__ out)
{
    extern __shared__ __align__(16) float sm[];
    float* PA   = sm + M_PA;
    float* MRTB = sm + M_MRTB;
    float* CVEC = sm + M_CVEC;
    float* ZS   = sm + M_ZS;
    float* ZSR  = sm + M_ZSR;
    float* XWR  = sm + M_XWR;
    float* HRB  = sm + M_HRB;
    float* HWB  = sm + M_HWB;
    float* EE   = sm + M_EE;
    float* ONXL = sm + M_ONXL;
    float* SB   = sm + M_SB;
    float* HOB  = sm + M_HOB;
    const uint2* W2u = reinterpret_cast<const uint2*>(sm + M_W2);  // 64 uint2/col
    const uint2* EUu = reinterpret_cast<const uint2*>(sm + M_EU);  // 32 uint2/col
    const uint2* URu = reinterpret_cast<const uint2*>(sm + M_UR);  // 32 uint2/col

    int tid = threadIdx.x, lane = tid & 31, warp = tid >> 5;
    uint32_t rank = ctarank();
    int b = blockIdx.x >> 2;
    int r0 = warp*4;

    uint32_t mrt_bar = smem_u32(sm + M_MB);
    uint32_t hwbar[2] = { smem_u32(sm + M_MB + 2), smem_u32(sm + M_MB + 4) };
    uint32_t hrbar[2] = { smem_u32(sm + M_MB + 6), smem_u32(sm + M_MB + 8) };
    if (tid == 0) {
        mbar_init(mrt_bar, 1);
        mbar_init(hwbar[0], 1); mbar_init(hwbar[1], 1);
        mbar_init(hrbar[0], 1); mbar_init(hrbar[1], 1);
    }

    const float* xwb = g_xw + (long)b*LL*GG;

    // weight slices -> smem (fp16)
    {
        uint4* dst = reinterpret_cast<uint4*>(sm + M_W2);
        const uint4* src = reinterpret_cast<const uint4*>(g_W2Th) + (long)rank*4096;
        for (int i = tid; i < 4096; i += 512) dst[i] = src[i];
        uint4* dstE = reinterpret_cast<uint4*>(sm + M_EU);
        const uint4* srcE = reinterpret_cast<const uint4*>(g_ETh) + (long)rank*2048;
        for (int i = tid; i < 2048; i += 512) dstE[i] = srcE[i];
        uint4* dstU = reinterpret_cast<uint4*>(sm + M_UR);
        const uint4* srcU = reinterpret_cast<const uint4*>(g_URh) + (long)rank*2048;
        for (int i = tid; i < 2048; i += 512) dstU[i] = srcU[i];
    }
    // mem slice -> REGISTERS: warp owns rows r0..r0+3 (global rows rank*64+...)
    float4 m[4];
    {
        const float* xb = x + ((long)b*LL + rank*64)*DD;
        #pragma unroll
        for (int li = 0; li < 4; li++)
            m[li] = *reinterpret_cast<const float4*>(xb + (r0 + li)*DD + lane*4);
    }
    if (tid < 256) HWB[tid] = 0.f;
    if (tid < 128) {
        // reader step 0: h=0 so z = xw(0) only; compute o_0 and c_r(0)
        float zi = xwb[tid], zg = xwb[256 + tid], zo = xwb[384 + tid];
        float c0 = hsig(zi) * tanh_fast(zg);
        float o0 = hsig(zo) * tanh_fast(c0);
        HRB[128 + tid] = o0;   // prev buf for t=0
        HRB[tid] = 0.f;
        ZSR[tid] = c0;         // stash c_r(0)
        XWR[tid] = xwb[GG + (tid >> 5)*128 + rank*32 + (tid & 31)];
        CVEC[tid] = g_cvec[(tid >> 5)*128 + rank*32 + (tid & 31)];
    }
    float cst_w = 0.f, cst_r = 0.f;
    __syncthreads();
    if (warp == 2) cst_r = ZSR[rank*32 + lane];
    CLUSTER_SYNC_();

    uint32_t r_mrtb[4], r_sb[4], r_mbar[4];
    uint32_t r_hwb[2][4], r_hwbar[2][4], r_hob[4];
    uint32_t r_hrb[2][4], r_hrbar[2][4];
    #pragma unroll
    for (int q = 0; q < 4; q++) {
        uint32_t pr = (rank + 1 + q) & 3;   // q=3 -> self
        r_mrtb[q] = mapa_u32(smem_u32(MRTB), pr);
        r_sb[q]   = mapa_u32(smem_u32(SB), pr);
        r_mbar[q] = mapa_u32(mrt_bar, pr);
        r_hwbar[0][q] = mapa_u32(hwbar[0], pr);
        r_hwbar[1][q] = mapa_u32(hwbar[1], pr);
        r_hwb[0][q]   = mapa_u32(smem_u32(HWB), pr);
        r_hwb[1][q]   = mapa_u32(smem_u32(HWB + 128), pr);
        r_hob[q]      = mapa_u32(smem_u32(HOB), pr);
        r_hrbar[0][q] = mapa_u32(hrbar[0], pr);
        r_hrbar[1][q] = mapa_u32(hrbar[1], pr);
        r_hrb[0][q]   = mapa_u32(smem_u32(HRB), pr);
        r_hrb[1][q]   = mapa_u32(smem_u32(HRB + 128), pr);
    }

    float4* PA4  = reinterpret_cast<float4*>(PA);
    const float2* PA2 = reinterpret_cast<const float2*>(PA);
    const float4* MRTB4 = reinterpret_cast<const float4*>(MRTB);

    // ---- initial scores: s_0 = o_0 . mem -> EE, PA (from registers) -------
    {
        float4 ov = reinterpret_cast<const float4*>(HRB + 128)[lane];
        float pr_[4];
        #pragma unroll
        for (int li = 0; li < 4; li++)
            pr_[li] = m[li].x*ov.x + m[li].y*ov.y + m[li].z*ov.z + m[li].w*ov.w;
        #pragma unroll
        for (int ofs = 16, n = 4; ofs >= 8; ofs >>= 1, n >>= 1) {
            int half = n >> 1;
            bool side = (lane & ofs) != 0;
            #pragma unroll
            for (int i = 0; i < 2; i++) {
                if (i < half) {
                    float send = side ? pr_[i] : pr_[i + half];
                    float recv = __shfl_xor_sync(0xffffffffu, send, ofs);
                    pr_[i] = (side ? pr_[i + half] : pr_[i]) + recv;
                }
            }
        }
        pr_[0] += __shfl_xor_sync(0xffffffffu, pr_[0], 4);
        pr_[0] += __shfl_xor_sync(0xffffffffu, pr_[0], 2);
        pr_[0] += __shfl_xor_sync(0xffffffffu, pr_[0], 1);
        if ((lane & 7) == 0) EE[r0 + ((lane >> 3) & 3)] = __expf(pr_[0]);
        __syncwarp();
        float4 pacc = make_float4(0.f, 0.f, 0.f, 0.f);
        #pragma unroll
        for (int li = 0; li < 4; li++) {
            float e = EE[r0 + li];
            pacc.x = fmaf(e, m[li].x, pacc.x);
            pacc.y = fmaf(e, m[li].y, pacc.y);
            pacc.z = fmaf(e, m[li].z, pacc.z);
            pacc.w = fmaf(e, m[li].w, pacc.w);
        }
        PA4[warp*32 + lane] = pacc;
    }
    __syncthreads();

    for (int t = 0; t < LL; t++) {
        int buf = t & 1, prev = buf ^ 1;
        int parh = (t >> 1) & 1, parm = t & 1;
        if (tid == 0) {
            mbar_arrive_expect(mrt_bar, 2064);       // 4 x (512 + 4)
            mbar_arrive_expect(hwbar[buf], 528);     // 4 x (128 + 4)
            mbar_arrive_expect(hrbar[buf], 512);     // 4 x 128
        }
        // ---- phase1: sends + prefetch, fused GEMVs (reader + Uw + E)
        if (tid < 64) {
            float2 p = make_float2(0.f, 0.f);
            #pragma unroll
            for (int w = 0; w < 16; w++) {
                float2 v = PA2[w*64 + tid];
                p.x += v.x; p.y += v.y;
            }
            #pragma unroll
            for (int q = 0; q < 4; q++)
                st_async_f64(r_mrtb[q] + (rank*128u + 2u*(uint32_t)tid)*4u, p.x, p.y, r_mbar[q]);
        } else if (tid >= 96 && tid < 128) {
            float v = EE[lane] + EE[32 + lane];
            #pragma unroll
            for (int o = 16; o > 0; o >>= 1) v += __shfl_xor_sync(0xffffffffu, v, o);
            if (lane == 0) {
                #pragma unroll
                for (int q = 0; q < 4; q++)
                    st_async_f32(r_sb[q] + rank*4u, v, r_mbar[q]);
            }
        } else if (tid >= 128 && tid < 192) {
            int i = (tid - 128)*2;
            int tn2 = (t + 2 < LL) ? t + 2 : LL - 1;
            XWR[prev*128 + i]     = xwb[tn2*GG + (i >> 5)*128 + rank*32 + (i & 31)];
            XWR[prev*128 + i + 1] = xwb[tn2*GG + ((i+1) >> 5)*128 + rank*32 + ((i+1) & 31)];
        }
        float accR[8], acc[8];
        {
            float4 ovt = reinterpret_cast<const float4*>(HRB + prev*128)[lane]; // o_t
            float4 hwv = reinterpret_cast<const float4*>(HWB + prev*128)[lane]; // h_w(t)
            #pragma unroll
            for (int i = 0; i < 8; i++) {
                int c = warp*8 + i;
                accR[i] = dot4_h(URu[c*32 + lane], ovt);
                acc[i]  = dot4_h(W2u[c*64 + lane], hwv) + dot4_h(EUu[c*32 + lane], ovt);
            }
            red8_store(accR, lane, ZSR + warp*8);
        }
        __syncthreads();                              // S1

        // ---- warp2: reader gates -> o_{t+1}, send hr
        if (warp == 2) {
            int j = lane;
            float i_ = hsig (ZSR[j]      + XWR[buf*128 + j]);
            float f_ = hsig (ZSR[32 + j] + XWR[buf*128 + 32 + j]);
            float g_ = tanh_fast(ZSR[64 + j] + XWR[buf*128 + 64 + j]);
            float o_ = hsig (ZSR[96 + j] + XWR[buf*128 + 96 + j]);
            cst_r = f_*cst_r + i_*g_;
            float hr = o_ * tanh_fast(cst_r);
            ONXL[j] = hr;
            float hn = __shfl_xor_sync(0xffffffffu, hr, 1);
            if ((j & 1) == 0) {
                #pragma unroll
                for (int q = 0; q < 4; q++)
                    st_async_f64(r_hrb[buf][q] + (rank*32u + (uint32_t)j)*4u, hr, hn, r_hrbar[buf][q]);
            }
        }

        // ---- phase3 (all): wait mrt; inv; F GEMV on unnormalized P; reduce
        mbar_wait(mrt_bar, parm);
        float inv = 1.0f / (SB[0] + SB[1] + SB[2] + SB[3]);
        {
            float4 mvP = MRTB4[lane];
            {
                float4 v1 = MRTB4[32 + lane], v2 = MRTB4[64 + lane], v3 = MRTB4[96 + lane];
                mvP.x += v1.x + v2.x + v3.x;
                mvP.y += v1.y + v2.y + v3.y;
                mvP.z += v1.z + v2.z + v3.z;
                mvP.w += v1.w + v2.w + v3.w;
            }
            #pragma unroll
            for (int i = 0; i < 8; i++) {
                float f = dot4_h(W2u[(warp*8 + i)*64 + 32 + lane], mvP);
                acc[i] = fmaf(f, inv, acc[i]);
            }
            red8_store(acc, lane, ZS + warp*8);
        }
        __syncthreads();                              // S2

        // ---- warp0: writer gates + h/ho send
        if (warp == 0) {
            int j = lane;
            float i_ = hsig (ZS[j]      + CVEC[j]);
            float f_ = hsig (ZS[32 + j] + CVEC[32 + j]);
            float g_ = tanh_fast(ZS[64 + j] + CVEC[64 + j]);
            float o_ = hsig (ZS[96 + j] + CVEC[96 + j]);
            cst_w = f_*cst_w + i_*g_;
            float h = o_ * tanh_fast(cst_w);
            if (t == LL - 1) out[b*DD + rank*32 + j] = h;
            float hop = h * ONXL[j];
            #pragma unroll
            for (int o = 16; o > 0; o >>= 1) hop += __shfl_xor_sync(0xffffffffu, hop, o);
            float hn = __shfl_xor_sync(0xffffffffu, h, 1);
            if ((j & 1) == 0) {
                #pragma unroll
                for (int q = 0; q < 4; q++)
                    st_async_f64(r_hwb[buf][q] + (rank*32u + (uint32_t)j)*4u, h, hn, r_hwbar[buf][q]);
            }
            if (j == 0) {
                #pragma unroll
                for (int q = 0; q < 4; q++)
                    st_async_f32(r_hob[q] + rank*4u, hop, r_hwbar[buf][q]);
            }
        }

        // ---- phase5a: snapshot old z; wait o_{t+1}; dots from registers
        float zold[4];
        #pragma unroll
        for (int li = 0; li < 4; li++) zold[li] = EE[r0 + li] * inv;

        mbar_wait(hrbar[buf], parh);
        float4 ov = reinterpret_cast<const float4*>(HRB + buf*128)[lane];  // o_{t+1}
        float dd[4];
        #pragma unroll
        for (int li = 0; li < 4; li++)
            dd[li] = m[li].x*ov.x + m[li].y*ov.y + m[li].z*ov.z + m[li].w*ov.w;
        #pragma unroll
        for (int ofs = 16, n = 4; ofs >= 8; ofs >>= 1, n >>= 1) {
            int half = n >> 1;
            bool side = (lane & ofs) != 0;
            #pragma unroll
            for (int i = 0; i < 2; i++) {
                if (i < half) {
                    float send = side ? dd[i] : dd[i + half];
                    float recv = __shfl_xor_sync(0xffffffffu, send, ofs);
                    dd[i] = (side ? dd[i + half] : dd[i]) + recv;
                }
            }
        }
        dd[0] += __shfl_xor_sync(0xffffffffu, dd[0], 4);
        dd[0] += __shfl_xor_sync(0xffffffffu, dd[0], 2);
        dd[0] += __shfl_xor_sync(0xffffffffu, dd[0], 1);

        mbar_wait(hwbar[buf], parh);

        // ---- phase5b: new scores via rank-1 identity; update m; PA partials
        float ho = HOB[0] + HOB[1] + HOB[2] + HOB[3];
        if ((lane & 7) == 0) {
            int li = (lane >> 3) & 3;
            float z = zold[li];
            EE[r0 + li] = __expf(dd[0] + z*(ho - dd[0]));
        }
        __syncwarp();
        {
            float4 hv = reinterpret_cast<const float4*>(HWB + buf*128)[lane];
            float4 pacc = make_float4(0.f, 0.f, 0.f, 0.f);
            float u = 0.f;
            #pragma unroll
            for (int li = 0; li < 4; li++) {
                float e = EE[r0 + li], z = zold[li];
                float w = e - e*z;           // e(1-z)
                pacc.x = fmaf(w, m[li].x, pacc.x);
                pacc.y = fmaf(w, m[li].y, pacc.y);
                pacc.z = fmaf(w, m[li].z, pacc.z);
                pacc.w = fmaf(w, m[li].w, pacc.w);
                u += e*z;
                m[li].x = fmaf(z, hv.x - m[li].x, m[li].x);
                m[li].y = fmaf(z, hv.y - m[li].y, m[li].y);
                m[li].z = fmaf(z, hv.z - m[li].z, m[li].z);
                m[li].w = fmaf(z, hv.w - m[li].w, m[li].w);
            }
            pacc.x = fmaf(u, hv.x, pacc.x);
            pacc.y = fmaf(u, hv.y, pacc.y);
            pacc.z = fmaf(u, hv.z, pacc.z);
            pacc.w = fmaf(u, hv.w, pacc.w);
            PA4[warp*32 + lane] = pacc;
        }
        __syncthreads();                              // SF
    }
    CLUSTER_SYNC_();
}

// ---------------------------------------------------------------------------
extern "C" void kernel_launch(void* const* d_in, const int* in_sizes, int n_in,
                              void* d_out, int out_size)
{
    const float* x  = (const float*)d_in[0];
    const float* Wr = (const float*)d_in[1];
    const float* Ur = (const float*)d_in[2];
    const float* br = (const float*)d_in[3];
    const float* Ww = (const float*)d_in[4];
    const float* Uw = (const float*)d_in[5];
    const float* bw = (const float*)d_in[6];
    const float* Wc = (const float*)d_in[7];
    const float* bc = (const float*)d_in[8];
    float* out = (float*)d_out;
    (void)in_sizes; (void)n_in; (void)out_size;

    void* p_xw;
    cudaGetSymbolAddress(&p_xw, g_xw);

    cudaFuncSetAttribute(fused_kernel,
                         cudaFuncAttributeMaxDynamicSharedMemorySize,
                         M_TOT * (int)sizeof(float));

    dim3 gdim(GG/64, (BB*LL)/64);

    // 0) xw = x @ Wr + br
    gemm_k128_n512<<<gdim, 256>>>(x, Wr, br, (float*)p_xw);
    // 1) fold weights: W2T (Uw,F), ET, URt, cvec
    prep_EF<<<DD, 512>>>(Wc, Ww, bc, bw, Uw, Ur);
    // 2) fused reader+writer scan (reader 1 step ahead; mem in registers)
    fused_kernel<<<4*BB, 512, M_TOT * (int)sizeof(float)>>>(x, out);
}